// round 14
// baseline (speedup 1.0000x reference)
#include <cuda_runtime.h>
#include <cuda_bf16.h>
#include <math_constants.h>
#include <cstdint>

#define NPTS   32768
#define KCODES 1024
#define DIM    256
#define HW     1024

#define OFF_ZQ    0ul
#define OFF_LOSS  8388608ul
#define OFF_IDX   8388609ul
#define OFF_EMB   8421377ul
#define OFF_CS    8683521ul
#define OFF_ES    8684545ul

#define EPS_GAP 3.5e-4f

// ---------------- device scratch ----------------
__device__ float g_zz[NPTS];
__device__ float g_ee[KCODES];
__device__ int   g_idx[NPTS];
__device__ int   g_fixlist[NPTS];
__device__ int   g_fixn;
__device__ unsigned long long g_best[NPTS];
__device__ float g_es[KCODES * DIM];
__device__ float g_counts[KCODES];
__device__ float g_loss;
__device__ float g_nsum;
__device__ float g_newcs[KCODES];

// compacted flagged points: z rows + zz, indexed by fixlist position
__device__ float g_zfix[NPTS * DIM];
__device__ float g_zzfix[NPTS];

// packed bf16 pairs
__device__ uint32_t g_zp[128 * NPTS];
__device__ uint32_t g_ep[128 * KCODES];

// ---------------- helpers ----------------
__device__ __forceinline__ uint32_t smem_u32(const void* p) {
    uint32_t a;
    asm("{ .reg .u64 t; cvta.to.shared.u64 t, %1; cvt.u32.u64 %0, t; }" : "=r"(a) : "l"(p));
    return a;
}
__device__ __forceinline__ uint32_t pack_bf16(float lo, float hi) {
    __nv_bfloat162 t = __floats2bfloat162_rn(lo, hi);
    return *reinterpret_cast<uint32_t*>(&t);
}
__device__ __forceinline__ void cp16(uint32_t dst, const void* src) {
    asm volatile("cp.async.cg.shared.global [%0], [%1], 16;" :: "r"(dst), "l"(src));
}
#define CP_COMMIT() asm volatile("cp.async.commit_group;" ::: "memory")
#define CP_WAIT1()  asm volatile("cp.async.wait_group 1;" ::: "memory")
#define CP_WAIT0()  asm volatile("cp.async.wait_group 0;" ::: "memory")

__device__ __forceinline__ void mma16(float* c, const uint32_t* a, uint32_t b0, uint32_t b1) {
    asm volatile(
        "mma.sync.aligned.m16n8k16.row.col.f32.bf16.bf16.f32 "
        "{%0,%1,%2,%3}, {%4,%5,%6,%7}, {%8,%9}, {%0,%1,%2,%3};"
        : "+f"(c[0]), "+f"(c[1]), "+f"(c[2]), "+f"(c[3])
        : "r"(a[0]), "r"(a[1]), "r"(a[2]), "r"(a[3]), "r"(b0), "r"(b1));
}

// top-2 insert, jnp.argmin tie-break
__device__ __forceinline__ void ins2(float& b0v, int& b0i, float& b1v, int& b1i,
                                     float v, int ix) {
    if (v < b0v || (v == b0v && ix < b0i)) {
        b1v = b0v; b1i = b0i; b0v = v; b0i = ix;
    } else if (v < b1v || (v == b1v && ix < b1i)) {
        b1v = v; b1i = ix;
    }
}
__device__ __forceinline__ void upd1(float& bv, int& bi, float v, int ix) {
    if (v < bv || (v == bv && ix < bi)) { bv = v; bi = ix; }
}

// ---------------- prep A: ||e||^2 | ||z||^2 + bf16 pack ----------------
__global__ __launch_bounds__(256) void k_prep_a(const float* __restrict__ E,
                                                const float* __restrict__ z) {
    int bid = blockIdx.x, tid = threadIdx.x;
    if (bid < 128) {
        int w = bid * 8 + (tid >> 5);
        int lane = tid & 31;
        const float* row = E + (size_t)w * DIM;
        float s = 0.f;
#pragma unroll
        for (int i = 0; i < 8; i++) { float v = row[lane + i * 32]; s = fmaf(v, v, s); }
#pragma unroll
        for (int o = 16; o; o >>= 1) s += __shfl_xor_sync(0xffffffffu, s, o);
        if (!lane) g_ee[w] = s;
    } else {
        int n = (bid - 128) * 256 + tid;
        int b = n >> 10, hw = n & 1023;
        const float* p = z + (size_t)b * DIM * HW + hw;
        float s = 0.f;
#pragma unroll 4
        for (int k2 = 0; k2 < 128; k2++) {
            float v0 = p[(size_t)(2 * k2) * HW];
            float v1 = p[(size_t)(2 * k2 + 1) * HW];
            s = fmaf(v0, v0, s);
            s = fmaf(v1, v1, s);
            g_zp[(size_t)k2 * NPTS + n] = pack_bf16(v0, v1);
        }
        g_zz[n] = s;
    }
}

// ---------------- prep BC: split E | zero accumulators | init g_best ----------------
__global__ __launch_bounds__(256) void k_prep_bc(const float* __restrict__ E) {
    int bid = blockIdx.x, tid = threadIdx.x;
    if (bid < 512) {
        int i = bid * 256 + tid;
        int code = i >> 7, k2 = i & 127;
        float v0 = E[(size_t)code * 256 + 2 * k2];
        float v1 = E[(size_t)code * 256 + 2 * k2 + 1];
        g_ep[k2 * KCODES + code] = pack_bf16(v0, v1);
    } else if (bid < 1541) {
        int i = (bid - 512) * 256 + tid;
        if (i < KCODES * DIM) g_es[i] = 0.f;
        else if (i < KCODES * DIM + KCODES) g_counts[i - KCODES * DIM] = 0.f;
        else if (i == KCODES * DIM + KCODES) g_loss = 0.f;
        else if (i == KCODES * DIM + KCODES + 1) g_nsum = 0.f;
        else if (i == KCODES * DIM + KCODES + 2) g_fixn = 0;
    } else {
        int i = (bid - 1541) * 256 + tid;
        g_best[i] = 0xFFFFFFFFFFFFFFFFull;
    }
}

// ---------------- single-pass bf16 mma GEMM + top-2 argmin + z gather ----------------
#define APITCH  136
#define BPITCH  136
#define SM_ZZ   0
#define SM_EE   512
#define SM_RED  4608
#define SM_A    8704
#define SM_B    (SM_A + 128 * APITCH * 4)
#define BSTAGE  (16 * BPITCH * 4)
#define SMEM_GEMM (SM_B + 3 * BSTAGE)

__device__ __forceinline__ void load_b_stage(uint32_t dstb, int g, int tid) {
    int nt1 = g >> 3, kc1 = g & 7;
    const uint32_t* ep = g_ep + (size_t)kc1 * 16 * KCODES + nt1 * 128;
#pragma unroll
    for (int j = 0; j < 2; j++) {
        int idx = tid + j * 256;
        int r = idx >> 5, cc = idx & 31;
        cp16(dstb + r * (BPITCH * 4) + cc * 16, ep + (size_t)r * KCODES + cc * 4);
    }
}

__global__ __launch_bounds__(256, 2) void k_gemm(const float* __restrict__ z,
                                                 float* __restrict__ out) {
    extern __shared__ uint8_t smem[];
    __shared__ int s_fN[128];
    __shared__ int s_fP[128];
    __shared__ int s_fcnt;
    uint32_t sb = smem_u32(smem);
    float* s_zz = reinterpret_cast<float*>(smem + SM_ZZ);
    float* s_ee = reinterpret_cast<float*>(smem + SM_EE);
    float* sB0v = reinterpret_cast<float*>(smem + SM_RED);
    int*   sB0i = reinterpret_cast<int*>(smem + SM_RED + 1024);
    float* sB1v = reinterpret_cast<float*>(smem + SM_RED + 2048);
    int*   sB1i = reinterpret_cast<int*>(smem + SM_RED + 3072);
    const uint32_t* sA = reinterpret_cast<const uint32_t*>(smem + SM_A);

    const int tid = threadIdx.x, cid = blockIdx.x;
    const int lane = tid & 31, w = tid >> 5;
    const int gq = lane >> 2, tig = lane & 3;
    const int mw = (w >> 1) * 32, nw = (w & 1) * 64;

    if (tid == 0) s_fcnt = 0;
    if (tid < 128) s_zz[tid] = g_zz[cid * 128 + tid];
#pragma unroll
    for (int i = 0; i < 4; i++) s_ee[tid + 256 * i] = g_ee[tid + 256 * i];

    {
        const uint32_t* zp = g_zp + (size_t)cid * 128;
#pragma unroll
        for (int j = 0; j < 16; j++) {
            int idx = tid + j * 256;
            int r = idx >> 5, cc = idx & 31;
            cp16(sb + SM_A + r * (APITCH * 4) + cc * 16, zp + (size_t)r * NPTS + cc * 4);
        }
    }
    load_b_stage(sb + SM_B, 0, tid);
    CP_COMMIT();
    load_b_stage(sb + SM_B + BSTAGE, 1, tid);
    CP_COMMIT();

    float acc[2][8][4];
#pragma unroll
    for (int mt = 0; mt < 2; mt++)
#pragma unroll
        for (int nt = 0; nt < 8; nt++)
#pragma unroll
            for (int q = 0; q < 4; q++) acc[mt][nt][q] = 0.f;
    float b0v[4], b1v[4]; int b0i[4], b1i[4];
#pragma unroll
    for (int i = 0; i < 4; i++) {
        b0v[i] = CUDART_INF_F; b0i[i] = 0x7fffffff;
        b1v[i] = CUDART_INF_F; b1i[i] = 0x7fffffff;
    }
    __syncthreads();
    float zzv[4];
#pragma unroll
    for (int mt = 0; mt < 2; mt++) {
        zzv[mt * 2]     = s_zz[mw + mt * 16 + gq];
        zzv[mt * 2 + 1] = s_zz[mw + mt * 16 + gq + 8];
    }

    int stage = 0;
    for (int it = 0; it < 64; it++) {
        if (it < 63) { CP_WAIT1(); } else { CP_WAIT0(); }
        __syncthreads();
        if (it + 2 < 64) {
            int st2 = stage + 2; if (st2 >= 3) st2 -= 3;
            load_b_stage(sb + SM_B + st2 * BSTAGE, it + 2, tid);
            CP_COMMIT();
        }

        const int kc = it & 7;
        const uint32_t* B = reinterpret_cast<const uint32_t*>(smem + SM_B + stage * BSTAGE);
        const uint32_t* Achunk = sA + (kc * 16) * APITCH;

#pragma unroll
        for (int ks = 0; ks < 2; ks++) {
            const int kb = ks * 8;
            uint32_t af[2][4];
#pragma unroll
            for (int mt = 0; mt < 2; mt++) {
                const uint32_t* Ap = Achunk + (kb + tig) * APITCH + mw + mt * 16 + gq;
                af[mt][0] = Ap[0];
                af[mt][1] = Ap[8];
                const uint32_t* Ap2 = Achunk + (kb + 4 + tig) * APITCH + mw + mt * 16 + gq;
                af[mt][2] = Ap2[0];
                af[mt][3] = Ap2[8];
            }
#pragma unroll
            for (int nt = 0; nt < 8; nt++) {
                uint32_t bf0 = B[(kb + tig) * BPITCH + nw + nt * 8 + gq];
                uint32_t bf1 = B[(kb + 4 + tig) * BPITCH + nw + nt * 8 + gq];
#pragma unroll
                for (int mt = 0; mt < 2; mt++) mma16(acc[mt][nt], af[mt], bf0, bf1);
            }
        }

        if (kc == 7) {
            int kt = it >> 3;
#pragma unroll
            for (int nt = 0; nt < 8; nt++) {
                int code0 = kt * 128 + nw + nt * 8 + 2 * tig;
                float2 ee2 = *reinterpret_cast<const float2*>(&s_ee[code0]);
#pragma unroll
                for (int mt = 0; mt < 2; mt++) {
                    float d0 = __fadd_rn(__fadd_rn(zzv[mt * 2], -__fmul_rn(2.0f, acc[mt][nt][0])), ee2.x);
                    float d1 = __fadd_rn(__fadd_rn(zzv[mt * 2], -__fmul_rn(2.0f, acc[mt][nt][1])), ee2.y);
                    float d2 = __fadd_rn(__fadd_rn(zzv[mt * 2 + 1], -__fmul_rn(2.0f, acc[mt][nt][2])), ee2.x);
                    float d3 = __fadd_rn(__fadd_rn(zzv[mt * 2 + 1], -__fmul_rn(2.0f, acc[mt][nt][3])), ee2.y);
                    int r0 = mt * 2, r1 = mt * 2 + 1;
                    ins2(b0v[r0], b0i[r0], b1v[r0], b1i[r0], d0, code0);
                    ins2(b0v[r0], b0i[r0], b1v[r0], b1i[r0], d1, code0 + 1);
                    ins2(b0v[r1], b0i[r1], b1v[r1], b1i[r1], d2, code0);
                    ins2(b0v[r1], b0i[r1], b1v[r1], b1i[r1], d3, code0 + 1);
                    acc[mt][nt][0] = 0.f; acc[mt][nt][1] = 0.f;
                    acc[mt][nt][2] = 0.f; acc[mt][nt][3] = 0.f;
                }
            }
        }
        stage++; if (stage == 3) stage = 0;
    }

    __syncthreads();
#pragma unroll
    for (int i = 0; i < 4; i++) {
        float v0 = b0v[i], v1 = b1v[i]; int i0 = b0i[i], i1 = b1i[i];
#pragma unroll
        for (int o = 1; o <= 2; o <<= 1) {
            float ov0 = __shfl_xor_sync(0xffffffffu, v0, o);
            int   oi0 = __shfl_xor_sync(0xffffffffu, i0, o);
            float ov1 = __shfl_xor_sync(0xffffffffu, v1, o);
            int   oi1 = __shfl_xor_sync(0xffffffffu, i1, o);
            ins2(v0, i0, v1, i1, ov0, oi0);
            ins2(v0, i0, v1, i1, ov1, oi1);
        }
        if (tig == 0) {
            int row = mw + (i >> 1) * 16 + gq + (i & 1) * 8;
            int half = (w & 1) * 128;
            sB0v[half + row] = v0; sB0i[half + row] = i0;
            sB1v[half + row] = v1; sB1i[half + row] = i1;
        }
    }
    __syncthreads();
    if (tid < 128) {
        float v0 = sB0v[tid], v1 = sB1v[tid];
        int i0 = sB0i[tid], i1 = sB1i[tid];
        ins2(v0, i0, v1, i1, sB0v[128 + tid], sB0i[128 + tid]);
        ins2(v0, i0, v1, i1, sB1v[128 + tid], sB1i[128 + tid]);
        int n = cid * 128 + tid;
        g_idx[n] = i0;
        out[OFF_IDX + n] = (float)i0;
        if (__fadd_rn(v1, -v0) < EPS_GAP) {
            int pos = atomicAdd(&g_fixn, 1);
            if (pos < NPTS) {
                g_fixlist[pos] = n;
                int l = atomicAdd(&s_fcnt, 1);
                s_fN[l] = n; s_fP[l] = pos;
            }
        }
    }
    // ---- gather flagged z rows into compacted g_zfix (coalesced consumer reads) ----
    __syncthreads();
    int fc = s_fcnt;
    for (int e = 0; e < fc; e++) {
        int n2 = s_fN[e], pos2 = s_fP[e];
        int b2 = n2 >> 10, hw2 = n2 & 1023;
        g_zfix[(size_t)pos2 * DIM + tid] = z[((size_t)b2 * DIM + tid) * HW + hw2];
        if (tid == 0) g_zzfix[pos2] = g_zz[n2];
    }
}

// ---------------- rescue v5: exact fp32 scan on compacted z, 8-way code split ----------------
// item = (32 pts x 128 codes). z from g_zfix (coalesced). Layout [row][65] float4.
#define FROW 65
#define SMEM_FIX (2 * 32 * FROW * 16 + 128 + 4096)   // 70784
__global__ __launch_bounds__(256) void k_fix(const float* __restrict__ E) {
    extern __shared__ uint8_t sm[];
    float4* s_z4 = reinterpret_cast<float4*>(sm);                    // [32][FROW]
    float4* s_e4 = reinterpret_cast<float4*>(sm + 32 * FROW * 16);   // [32][FROW]
    float*  s_zzl = reinterpret_cast<float*>(sm + 2 * 32 * FROW * 16);
    float*  s_rv = s_zzl + 32;
    int*    s_ri = reinterpret_cast<int*>(s_rv + 512);

    const int tid = threadIdx.x;
    const int tx = tid & 15, ty = tid >> 4;
    int cnt = min(g_fixn, NPTS);
    int nwork = ((cnt + 31) >> 5) * 8;

    for (int wi = blockIdx.x; wi < nwork; wi += gridDim.x) {
        int g = wi >> 3, oct = wi & 7;
        int base = g * 32;
        int np = min(32, cnt - base);
        // ---- fill z tile: coalesced from g_zfix ----
        {
            const float4* zf4 = reinterpret_cast<const float4*>(g_zfix);
#pragma unroll
            for (int j = 0; j < 8; j++) {
                int idx = tid + j * 256;
                int row = idx >> 6, c4 = idx & 63;
                int rl = (row < np) ? row : 0;
                s_z4[row * FROW + c4] = zf4[(size_t)(base + rl) * 64 + c4];
            }
            if (tid < 32) {
                int rl = (tid < np) ? tid : 0;
                s_zzl[tid] = g_zzfix[base + rl];
            }
        }

        float bv0 = CUDART_INF_F, bv1 = CUDART_INF_F;
        int bi0 = 0x7fffffff, bi1 = 0x7fffffff;

        for (int t = 0; t < 4; t++) {
            __syncthreads();
            int cbase = oct * 128 + t * 32;
            const float4* E4 = reinterpret_cast<const float4*>(E) + (size_t)cbase * 64;
#pragma unroll
            for (int j = 0; j < 8; j++) {
                int idx = tid + j * 256;
                int c = idx >> 6, k4 = idx & 63;
                s_e4[c * FROW + k4] = E4[c * 64 + k4];
            }
            __syncthreads();
            float a00 = 0.f, a01 = 0.f, a10 = 0.f, a11 = 0.f;
#pragma unroll 8
            for (int k4 = 0; k4 < 64; k4++) {
                float4 za = s_z4[ty * FROW + k4];
                float4 zb = s_z4[(ty + 16) * FROW + k4];
                float4 ea = s_e4[tx * FROW + k4];
                float4 eb = s_e4[(tx + 16) * FROW + k4];
                a00 = fmaf(za.x, ea.x, a00); a00 = fmaf(za.y, ea.y, a00);
                a00 = fmaf(za.z, ea.z, a00); a00 = fmaf(za.w, ea.w, a00);
                a01 = fmaf(za.x, eb.x, a01); a01 = fmaf(za.y, eb.y, a01);
                a01 = fmaf(za.z, eb.z, a01); a01 = fmaf(za.w, eb.w, a01);
                a10 = fmaf(zb.x, ea.x, a10); a10 = fmaf(zb.y, ea.y, a10);
                a10 = fmaf(zb.z, ea.z, a10); a10 = fmaf(zb.w, ea.w, a10);
                a11 = fmaf(zb.x, eb.x, a11); a11 = fmaf(zb.y, eb.y, a11);
                a11 = fmaf(zb.z, eb.z, a11); a11 = fmaf(zb.w, eb.w, a11);
            }
            int c0 = cbase + tx, c1 = cbase + tx + 16;
            float ee0 = g_ee[c0], ee1 = g_ee[c1];
            float zz0 = s_zzl[ty], zz1 = s_zzl[ty + 16];
            float d00 = __fadd_rn(__fadd_rn(zz0, -__fmul_rn(2.0f, a00)), ee0);
            float d01 = __fadd_rn(__fadd_rn(zz0, -__fmul_rn(2.0f, a01)), ee1);
            float d10 = __fadd_rn(__fadd_rn(zz1, -__fmul_rn(2.0f, a10)), ee0);
            float d11 = __fadd_rn(__fadd_rn(zz1, -__fmul_rn(2.0f, a11)), ee1);
            upd1(bv0, bi0, d00, c0); upd1(bv0, bi0, d01, c1);
            upd1(bv1, bi1, d10, c0); upd1(bv1, bi1, d11, c1);
        }
        __syncthreads();
        s_rv[ty * 16 + tx] = bv0;        s_ri[ty * 16 + tx] = bi0;
        s_rv[(ty + 16) * 16 + tx] = bv1; s_ri[(ty + 16) * 16 + tx] = bi1;
        __syncthreads();
        if (tid < 32 && tid < np) {
            float bv = s_rv[tid * 16]; int bi = s_ri[tid * 16];
#pragma unroll
            for (int k = 1; k < 16; k++)
                upd1(bv, bi, s_rv[tid * 16 + k], s_ri[tid * 16 + k]);
            int n = g_fixlist[base + tid];
            unsigned long long key =
                ((unsigned long long)__float_as_uint(bv) << 32) | (unsigned int)bi;
            atomicMin(&g_best[n], key);
        }
        __syncthreads();
    }
}

// ---------------- finalize rescued indices ----------------
__global__ __launch_bounds__(256) void k_fin(float* __restrict__ out) {
    int e = blockIdx.x * 256 + threadIdx.x;
    int cnt = min(g_fixn, NPTS);
    if (e < cnt) {
        int n = g_fixlist[e];
        int idx = (int)(unsigned int)(g_best[n] & 0xFFFFFFFFull);
        g_idx[n] = idx;
        out[OFF_IDX + n] = (float)idx;
    }
}

// ---------------- fused epilogue: gather z_q, loss, counts, embed_sum ----------------
__global__ __launch_bounds__(256)
void k_epi(const float* __restrict__ z, const float* __restrict__ E,
           float* __restrict__ out) {
    __shared__ float tile[64 * 129];
    __shared__ float lred[8];
    __shared__ int s_code[128];
    const int tid = threadIdx.x;
    const int n0 = blockIdx.x * 128;
    const int b = n0 >> 10, hw0 = n0 & 1023;
    const float* zb = z + (size_t)b * DIM * HW + hw0;
    float* ob = out + OFF_ZQ + (size_t)b * DIM * HW + hw0;
    const int w = tid >> 5, lane = tid & 31;
    float lacc = 0.f;

    if (tid < 128) s_code[tid] = g_idx[n0 + tid];

    for (int c = 0; c < 4; c++) {
#pragma unroll
        for (int r = 0; r < 32; r++) {
            int idx = tid + r * 256;
            int dd = idx >> 7, pt = idx & 127;
            tile[dd * 129 + pt] = zb[(size_t)(c * 64 + dd) * HW + pt];
        }
        __syncthreads();
        for (int q = 0; q < 16; q++) {
            int pt = w * 16 + q;
            int code = s_code[pt];
            int d = c * 64 + lane * 2;
            float2 ev = *reinterpret_cast<const float2*>(&E[(size_t)code * DIM + d]);
            float z0 = tile[(lane * 2) * 129 + pt];
            float z1 = tile[(lane * 2 + 1) * 129 + pt];
            float d0 = __fadd_rn(z0, -ev.x);
            float d1 = __fadd_rn(z1, -ev.y);
            lacc = fmaf(d0, d0, lacc);
            lacc = fmaf(d1, d1, lacc);
            float o0 = __fadd_rn(z0, __fadd_rn(ev.x, -z0));
            float o1 = __fadd_rn(z1, __fadd_rn(ev.y, -z1));
            tile[(lane * 2) * 129 + pt] = o0;
            tile[(lane * 2 + 1) * 129 + pt] = o1;
            atomicAdd(reinterpret_cast<float2*>(&g_es[(size_t)code * DIM + d]),
                      make_float2(z0, z1));
        }
        __syncthreads();
#pragma unroll
        for (int r = 0; r < 32; r++) {
            int idx = tid + r * 256;
            int dd = idx >> 7, pt = idx & 127;
            ob[(size_t)(c * 64 + dd) * HW + pt] = tile[dd * 129 + pt];
        }
        __syncthreads();
    }
    if (tid < 128) atomicAdd(&g_counts[s_code[tid]], 1.0f);
#pragma unroll
    for (int o = 16; o; o >>= 1) lacc += __shfl_xor_sync(0xffffffffu, lacc, o);
    if (!lane) lred[w] = lacc;
    __syncthreads();
    if (tid == 0) {
        float s = 0.f;
#pragma unroll
        for (int i = 0; i < 8; i++) s += lred[i];
        atomicAdd(&g_loss, s);
    }
}

// ---------------- new_cs + n + loss scalar ----------------
__global__ void k4a(const float* __restrict__ ema_cs, float* __restrict__ out) {
    __shared__ float red[32];
    int k = threadIdx.x;
    float ncs = __fadd_rn(__fmul_rn(0.99f, ema_cs[k]), __fmul_rn(0.01f, g_counts[k]));
    g_newcs[k] = ncs;
    out[OFF_CS + k] = ncs;
    float s = ncs;
#pragma unroll
    for (int o = 16; o; o >>= 1) s += __shfl_xor_sync(0xffffffffu, s, o);
    if ((k & 31) == 0) red[k >> 5] = s;
    __syncthreads();
    if (k < 32) {
        float v = red[k];
#pragma unroll
        for (int o = 16; o; o >>= 1) v += __shfl_xor_sync(0xffffffffu, v, o);
        if (!k) {
            g_nsum = v;
            out[OFF_LOSS] = g_loss * (1.0f / 8388608.0f);
        }
    }
}

// ---------------- new_es + new_embedding ----------------
__global__ void k4b(const float* __restrict__ ema_es, float* __restrict__ out) {
    int k = blockIdx.x, d = threadIdx.x;
    size_t i = (size_t)k * DIM + d;
    float es = __fadd_rn(__fmul_rn(0.99f, ema_es[i]), __fmul_rn(0.01f, g_es[i]));
    out[OFF_ES + i] = es;
    float n = g_nsum;
    float cs = __fmul_rn(__fdiv_rn(__fadd_rn(g_newcs[k], 1e-5f),
                                   __fadd_rn(n, 0.01024f)), n);
    out[OFF_EMB + i] = __fdiv_rn(es, cs);
}

extern "C" void kernel_launch(void* const* d_in, const int* in_sizes, int n_in,
                              void* d_out, int out_size) {
    const float* z      = (const float*)d_in[0];
    const float* E      = (const float*)d_in[1];
    const float* ema_cs = (const float*)d_in[2];
    const float* ema_es = (const float*)d_in[3];
    float* out = (float*)d_out;

    cudaFuncSetAttribute(k_gemm, cudaFuncAttributeMaxDynamicSharedMemorySize, SMEM_GEMM);
    cudaFuncSetAttribute(k_fix, cudaFuncAttributeMaxDynamicSharedMemorySize, SMEM_FIX);

    k_prep_a<<<256, 256>>>(E, z);                // 1: ee + zz+pack
    k_prep_bc<<<1669, 256>>>(E);                 // 2: split E + zero + g_best init
    k_gemm<<<256, 256, SMEM_GEMM>>>(z, out);     // 3: gemm + top2 + z gather
    k_fix<<<512, 256, SMEM_FIX>>>(E);            // 4  <- ncu captures this
    k_fin<<<128, 256>>>(out);                    // 5
    k_epi<<<NPTS / 128, 256>>>(z, E, out);       // 6
    k4a<<<1, 1024>>>(ema_cs, out);               // 7
    k4b<<<KCODES, DIM>>>(ema_es, out);           // 8
}

// round 15
// speedup vs baseline: 1.0414x; 1.0414x over previous
#include <cuda_runtime.h>
#include <cuda_bf16.h>
#include <math_constants.h>
#include <cstdint>

#define NPTS   32768
#define KCODES 1024
#define DIM    256
#define HW     1024

#define OFF_ZQ    0ul
#define OFF_LOSS  8388608ul
#define OFF_IDX   8388609ul
#define OFF_EMB   8421377ul
#define OFF_CS    8683521ul
#define OFF_ES    8684545ul

#define EPS_GAP 3.5e-4f

// ---------------- device scratch ----------------
__device__ float g_zz[NPTS];
__device__ float g_ee[KCODES];
__device__ int   g_idx[NPTS];
__device__ int   g_fixlist[NPTS];
__device__ int   g_fixn;
__device__ unsigned long long g_best[NPTS];
__device__ float g_es[KCODES * DIM];
__device__ float g_counts[KCODES];
__device__ float g_loss;
__device__ float g_nsum;
__device__ float g_newcs[KCODES];

// compacted flagged points: z rows + zz, indexed by fixlist position
__device__ float g_zfix[NPTS * DIM];
__device__ float g_zzfix[NPTS];

// packed bf16 pairs
__device__ uint32_t g_zp[128 * NPTS];
__device__ uint32_t g_ep[128 * KCODES];

// ---------------- helpers ----------------
__device__ __forceinline__ uint32_t smem_u32(const void* p) {
    uint32_t a;
    asm("{ .reg .u64 t; cvta.to.shared.u64 t, %1; cvt.u32.u64 %0, t; }" : "=r"(a) : "l"(p));
    return a;
}
__device__ __forceinline__ uint32_t pack_bf16(float lo, float hi) {
    __nv_bfloat162 t = __floats2bfloat162_rn(lo, hi);
    return *reinterpret_cast<uint32_t*>(&t);
}
__device__ __forceinline__ void cp16(uint32_t dst, const void* src) {
    asm volatile("cp.async.cg.shared.global [%0], [%1], 16;" :: "r"(dst), "l"(src));
}
#define CP_COMMIT() asm volatile("cp.async.commit_group;" ::: "memory")
#define CP_WAIT1()  asm volatile("cp.async.wait_group 1;" ::: "memory")
#define CP_WAIT0()  asm volatile("cp.async.wait_group 0;" ::: "memory")

__device__ __forceinline__ void mma16(float* c, const uint32_t* a, uint32_t b0, uint32_t b1) {
    asm volatile(
        "mma.sync.aligned.m16n8k16.row.col.f32.bf16.bf16.f32 "
        "{%0,%1,%2,%3}, {%4,%5,%6,%7}, {%8,%9}, {%0,%1,%2,%3};"
        : "+f"(c[0]), "+f"(c[1]), "+f"(c[2]), "+f"(c[3])
        : "r"(a[0]), "r"(a[1]), "r"(a[2]), "r"(a[3]), "r"(b0), "r"(b1));
}

// top-2 insert, jnp.argmin tie-break
__device__ __forceinline__ void ins2(float& b0v, int& b0i, float& b1v, int& b1i,
                                     float v, int ix) {
    if (v < b0v || (v == b0v && ix < b0i)) {
        b1v = b0v; b1i = b0i; b0v = v; b0i = ix;
    } else if (v < b1v || (v == b1v && ix < b1i)) {
        b1v = v; b1i = ix;
    }
}
__device__ __forceinline__ void upd1(float& bv, int& bi, float v, int ix) {
    if (v < bv || (v == bv && ix < bi)) { bv = v; bi = ix; }
}

// ---------------- prep A: ||e||^2 | ||z||^2 + bf16 pack ----------------
__global__ __launch_bounds__(256) void k_prep_a(const float* __restrict__ E,
                                                const float* __restrict__ z) {
    int bid = blockIdx.x, tid = threadIdx.x;
    if (bid < 128) {
        int w = bid * 8 + (tid >> 5);
        int lane = tid & 31;
        const float* row = E + (size_t)w * DIM;
        float s = 0.f;
#pragma unroll
        for (int i = 0; i < 8; i++) { float v = row[lane + i * 32]; s = fmaf(v, v, s); }
#pragma unroll
        for (int o = 16; o; o >>= 1) s += __shfl_xor_sync(0xffffffffu, s, o);
        if (!lane) g_ee[w] = s;
    } else {
        int n = (bid - 128) * 256 + tid;
        int b = n >> 10, hw = n & 1023;
        const float* p = z + (size_t)b * DIM * HW + hw;
        float s = 0.f;
#pragma unroll 4
        for (int k2 = 0; k2 < 128; k2++) {
            float v0 = p[(size_t)(2 * k2) * HW];
            float v1 = p[(size_t)(2 * k2 + 1) * HW];
            s = fmaf(v0, v0, s);
            s = fmaf(v1, v1, s);
            g_zp[(size_t)k2 * NPTS + n] = pack_bf16(v0, v1);
        }
        g_zz[n] = s;
    }
}

// ---------------- prep BC: split E | zero accumulators | init g_best ----------------
__global__ __launch_bounds__(256) void k_prep_bc(const float* __restrict__ E) {
    int bid = blockIdx.x, tid = threadIdx.x;
    if (bid < 512) {
        int i = bid * 256 + tid;
        int code = i >> 7, k2 = i & 127;
        float v0 = E[(size_t)code * 256 + 2 * k2];
        float v1 = E[(size_t)code * 256 + 2 * k2 + 1];
        g_ep[k2 * KCODES + code] = pack_bf16(v0, v1);
    } else if (bid < 1541) {
        int i = (bid - 512) * 256 + tid;
        if (i < KCODES * DIM) g_es[i] = 0.f;
        else if (i < KCODES * DIM + KCODES) g_counts[i - KCODES * DIM] = 0.f;
        else if (i == KCODES * DIM + KCODES) g_loss = 0.f;
        else if (i == KCODES * DIM + KCODES + 1) g_nsum = 0.f;
        else if (i == KCODES * DIM + KCODES + 2) g_fixn = 0;
    } else {
        int i = (bid - 1541) * 256 + tid;
        g_best[i] = 0xFFFFFFFFFFFFFFFFull;
    }
}

// ---------------- single-pass bf16 mma GEMM + top-2 argmin + z gather ----------------
#define APITCH  136
#define BPITCH  136
#define SM_ZZ   0
#define SM_EE   512
#define SM_RED  4608
#define SM_A    8704
#define SM_B    (SM_A + 128 * APITCH * 4)
#define BSTAGE  (16 * BPITCH * 4)
#define SMEM_GEMM (SM_B + 3 * BSTAGE)

__device__ __forceinline__ void load_b_stage(uint32_t dstb, int g, int tid) {
    int nt1 = g >> 3, kc1 = g & 7;
    const uint32_t* ep = g_ep + (size_t)kc1 * 16 * KCODES + nt1 * 128;
#pragma unroll
    for (int j = 0; j < 2; j++) {
        int idx = tid + j * 256;
        int r = idx >> 5, cc = idx & 31;
        cp16(dstb + r * (BPITCH * 4) + cc * 16, ep + (size_t)r * KCODES + cc * 4);
    }
}

__global__ __launch_bounds__(256, 2) void k_gemm(const float* __restrict__ z,
                                                 float* __restrict__ out) {
    extern __shared__ uint8_t smem[];
    __shared__ int s_fN[128];
    __shared__ int s_fP[128];
    __shared__ int s_fcnt;
    uint32_t sb = smem_u32(smem);
    float* s_zz = reinterpret_cast<float*>(smem + SM_ZZ);
    float* s_ee = reinterpret_cast<float*>(smem + SM_EE);
    float* sB0v = reinterpret_cast<float*>(smem + SM_RED);
    int*   sB0i = reinterpret_cast<int*>(smem + SM_RED + 1024);
    float* sB1v = reinterpret_cast<float*>(smem + SM_RED + 2048);
    int*   sB1i = reinterpret_cast<int*>(smem + SM_RED + 3072);
    const uint32_t* sA = reinterpret_cast<const uint32_t*>(smem + SM_A);

    const int tid = threadIdx.x, cid = blockIdx.x;
    const int lane = tid & 31, w = tid >> 5;
    const int gq = lane >> 2, tig = lane & 3;
    const int mw = (w >> 1) * 32, nw = (w & 1) * 64;

    if (tid == 0) s_fcnt = 0;
    if (tid < 128) s_zz[tid] = g_zz[cid * 128 + tid];
#pragma unroll
    for (int i = 0; i < 4; i++) s_ee[tid + 256 * i] = g_ee[tid + 256 * i];

    {
        const uint32_t* zp = g_zp + (size_t)cid * 128;
#pragma unroll
        for (int j = 0; j < 16; j++) {
            int idx = tid + j * 256;
            int r = idx >> 5, cc = idx & 31;
            cp16(sb + SM_A + r * (APITCH * 4) + cc * 16, zp + (size_t)r * NPTS + cc * 4);
        }
    }
    load_b_stage(sb + SM_B, 0, tid);
    CP_COMMIT();
    load_b_stage(sb + SM_B + BSTAGE, 1, tid);
    CP_COMMIT();

    float acc[2][8][4];
#pragma unroll
    for (int mt = 0; mt < 2; mt++)
#pragma unroll
        for (int nt = 0; nt < 8; nt++)
#pragma unroll
            for (int q = 0; q < 4; q++) acc[mt][nt][q] = 0.f;
    float b0v[4], b1v[4]; int b0i[4], b1i[4];
#pragma unroll
    for (int i = 0; i < 4; i++) {
        b0v[i] = CUDART_INF_F; b0i[i] = 0x7fffffff;
        b1v[i] = CUDART_INF_F; b1i[i] = 0x7fffffff;
    }
    __syncthreads();
    float zzv[4];
#pragma unroll
    for (int mt = 0; mt < 2; mt++) {
        zzv[mt * 2]     = s_zz[mw + mt * 16 + gq];
        zzv[mt * 2 + 1] = s_zz[mw + mt * 16 + gq + 8];
    }

    int stage = 0;
    for (int it = 0; it < 64; it++) {
        if (it < 63) { CP_WAIT1(); } else { CP_WAIT0(); }
        __syncthreads();
        if (it + 2 < 64) {
            int st2 = stage + 2; if (st2 >= 3) st2 -= 3;
            load_b_stage(sb + SM_B + st2 * BSTAGE, it + 2, tid);
            CP_COMMIT();
        }

        const int kc = it & 7;
        const uint32_t* B = reinterpret_cast<const uint32_t*>(smem + SM_B + stage * BSTAGE);
        const uint32_t* Achunk = sA + (kc * 16) * APITCH;

#pragma unroll
        for (int ks = 0; ks < 2; ks++) {
            const int kb = ks * 8;
            uint32_t af[2][4];
#pragma unroll
            for (int mt = 0; mt < 2; mt++) {
                const uint32_t* Ap = Achunk + (kb + tig) * APITCH + mw + mt * 16 + gq;
                af[mt][0] = Ap[0];
                af[mt][1] = Ap[8];
                const uint32_t* Ap2 = Achunk + (kb + 4 + tig) * APITCH + mw + mt * 16 + gq;
                af[mt][2] = Ap2[0];
                af[mt][3] = Ap2[8];
            }
#pragma unroll
            for (int nt = 0; nt < 8; nt++) {
                uint32_t bf0 = B[(kb + tig) * BPITCH + nw + nt * 8 + gq];
                uint32_t bf1 = B[(kb + 4 + tig) * BPITCH + nw + nt * 8 + gq];
#pragma unroll
                for (int mt = 0; mt < 2; mt++) mma16(acc[mt][nt], af[mt], bf0, bf1);
            }
        }

        if (kc == 7) {
            int kt = it >> 3;
#pragma unroll
            for (int nt = 0; nt < 8; nt++) {
                int code0 = kt * 128 + nw + nt * 8 + 2 * tig;
                float2 ee2 = *reinterpret_cast<const float2*>(&s_ee[code0]);
#pragma unroll
                for (int mt = 0; mt < 2; mt++) {
                    float d0 = __fadd_rn(__fadd_rn(zzv[mt * 2], -__fmul_rn(2.0f, acc[mt][nt][0])), ee2.x);
                    float d1 = __fadd_rn(__fadd_rn(zzv[mt * 2], -__fmul_rn(2.0f, acc[mt][nt][1])), ee2.y);
                    float d2 = __fadd_rn(__fadd_rn(zzv[mt * 2 + 1], -__fmul_rn(2.0f, acc[mt][nt][2])), ee2.x);
                    float d3 = __fadd_rn(__fadd_rn(zzv[mt * 2 + 1], -__fmul_rn(2.0f, acc[mt][nt][3])), ee2.y);
                    int r0 = mt * 2, r1 = mt * 2 + 1;
                    ins2(b0v[r0], b0i[r0], b1v[r0], b1i[r0], d0, code0);
                    ins2(b0v[r0], b0i[r0], b1v[r0], b1i[r0], d1, code0 + 1);
                    ins2(b0v[r1], b0i[r1], b1v[r1], b1i[r1], d2, code0);
                    ins2(b0v[r1], b0i[r1], b1v[r1], b1i[r1], d3, code0 + 1);
                    acc[mt][nt][0] = 0.f; acc[mt][nt][1] = 0.f;
                    acc[mt][nt][2] = 0.f; acc[mt][nt][3] = 0.f;
                }
            }
        }
        stage++; if (stage == 3) stage = 0;
    }

    __syncthreads();
#pragma unroll
    for (int i = 0; i < 4; i++) {
        float v0 = b0v[i], v1 = b1v[i]; int i0 = b0i[i], i1 = b1i[i];
#pragma unroll
        for (int o = 1; o <= 2; o <<= 1) {
            float ov0 = __shfl_xor_sync(0xffffffffu, v0, o);
            int   oi0 = __shfl_xor_sync(0xffffffffu, i0, o);
            float ov1 = __shfl_xor_sync(0xffffffffu, v1, o);
            int   oi1 = __shfl_xor_sync(0xffffffffu, i1, o);
            ins2(v0, i0, v1, i1, ov0, oi0);
            ins2(v0, i0, v1, i1, ov1, oi1);
        }
        if (tig == 0) {
            int row = mw + (i >> 1) * 16 + gq + (i & 1) * 8;
            int half = (w & 1) * 128;
            sB0v[half + row] = v0; sB0i[half + row] = i0;
            sB1v[half + row] = v1; sB1i[half + row] = i1;
        }
    }
    __syncthreads();
    if (tid < 128) {
        float v0 = sB0v[tid], v1 = sB1v[tid];
        int i0 = sB0i[tid], i1 = sB1i[tid];
        ins2(v0, i0, v1, i1, sB0v[128 + tid], sB0i[128 + tid]);
        ins2(v0, i0, v1, i1, sB1v[128 + tid], sB1i[128 + tid]);
        int n = cid * 128 + tid;
        g_idx[n] = i0;
        out[OFF_IDX + n] = (float)i0;
        if (__fadd_rn(v1, -v0) < EPS_GAP) {
            int pos = atomicAdd(&g_fixn, 1);
            if (pos < NPTS) {
                g_fixlist[pos] = n;
                int l = atomicAdd(&s_fcnt, 1);
                s_fN[l] = n; s_fP[l] = pos;
            }
        }
    }
    // ---- gather flagged z rows into compacted g_zfix (coalesced consumer reads) ----
    __syncthreads();
    int fc = s_fcnt;
    for (int e = 0; e < fc; e++) {
        int n2 = s_fN[e], pos2 = s_fP[e];
        int b2 = n2 >> 10, hw2 = n2 & 1023;
        g_zfix[(size_t)pos2 * DIM + tid] = z[((size_t)b2 * DIM + tid) * HW + hw2];
        if (tid == 0) g_zzfix[pos2] = g_zz[n2];
    }
}

// ---------------- rescue v6: exact fp32 scan, k4-major e tiles, 16-way code split ----------------
// item = (32 pts x 64 codes). z [row][FROW=65] float4 (broadcast reads);
// e [k4][EROW=33] float4 (contiguous conflict-free reads). 2 chunks of 32 codes per item.
#define FROW 65
#define EROW 33
#define SMFX_Z 0
#define SMFX_E (32 * FROW * 16)                     // 33280
#define SMFX_ZZ (SMFX_E + 64 * EROW * 16)           // 67072
#define SMFX_RV (SMFX_ZZ + 128)
#define SMFX_RI (SMFX_RV + 2048)
#define SMEM_FIX (SMFX_RI + 2048)                   // 71296
__global__ __launch_bounds__(256) void k_fix(const float* __restrict__ E) {
    extern __shared__ uint8_t sm[];
    float4* s_z4 = reinterpret_cast<float4*>(sm + SMFX_Z);     // [32][FROW]
    float4* s_e4 = reinterpret_cast<float4*>(sm + SMFX_E);     // [64][EROW]
    float*  s_zzl = reinterpret_cast<float*>(sm + SMFX_ZZ);
    float*  s_rv = reinterpret_cast<float*>(sm + SMFX_RV);     // [32][16]
    int*    s_ri = reinterpret_cast<int*>(sm + SMFX_RI);

    const int tid = threadIdx.x;
    const int tx = tid & 15, ty = tid >> 4;
    int cnt = min(g_fixn, NPTS);
    int nwork = ((cnt + 31) >> 5) * 16;

    for (int wi = blockIdx.x; wi < nwork; wi += gridDim.x) {
        int g = wi >> 4, seg = wi & 15;              // seg: 64-code segment
        int base = g * 32;
        int np = min(32, cnt - base);
        // ---- fill z tile: coalesced from g_zfix ----
        {
            const float4* zf4 = reinterpret_cast<const float4*>(g_zfix);
#pragma unroll
            for (int j = 0; j < 8; j++) {
                int idx = tid + j * 256;
                int row = idx >> 6, c4 = idx & 63;
                int rl = (row < np) ? row : 0;
                s_z4[row * FROW + c4] = zf4[(size_t)(base + rl) * 64 + c4];
            }
            if (tid < 32) {
                int rl = (tid < np) ? tid : 0;
                s_zzl[tid] = g_zzfix[base + rl];
            }
        }

        float bv0 = CUDART_INF_F, bv1 = CUDART_INF_F;
        int bi0 = 0x7fffffff, bi1 = 0x7fffffff;

        for (int t = 0; t < 2; t++) {
            __syncthreads();
            int cbase = seg * 64 + t * 32;
            const float4* E4 = reinterpret_cast<const float4*>(E) + (size_t)cbase * 64;
            // fill e chunk k4-major: global coalesced, smem write conflicted (amortized)
#pragma unroll
            for (int j = 0; j < 8; j++) {
                int idx = tid + j * 256;
                int c = idx >> 6, k4 = idx & 63;
                s_e4[k4 * EROW + c] = E4[c * 64 + k4];
            }
            __syncthreads();
            float a00 = 0.f, a01 = 0.f, a10 = 0.f, a11 = 0.f;
#pragma unroll 8
            for (int k4 = 0; k4 < 64; k4++) {
                float4 za = s_z4[ty * FROW + k4];
                float4 zb = s_z4[(ty + 16) * FROW + k4];
                float4 ea = s_e4[k4 * EROW + tx];
                float4 eb = s_e4[k4 * EROW + tx + 16];
                a00 = fmaf(za.x, ea.x, a00); a00 = fmaf(za.y, ea.y, a00);
                a00 = fmaf(za.z, ea.z, a00); a00 = fmaf(za.w, ea.w, a00);
                a01 = fmaf(za.x, eb.x, a01); a01 = fmaf(za.y, eb.y, a01);
                a01 = fmaf(za.z, eb.z, a01); a01 = fmaf(za.w, eb.w, a01);
                a10 = fmaf(zb.x, ea.x, a10); a10 = fmaf(zb.y, ea.y, a10);
                a10 = fmaf(zb.z, ea.z, a10); a10 = fmaf(zb.w, ea.w, a10);
                a11 = fmaf(zb.x, eb.x, a11); a11 = fmaf(zb.y, eb.y, a11);
                a11 = fmaf(zb.z, eb.z, a11); a11 = fmaf(zb.w, eb.w, a11);
            }
            int c0 = cbase + tx, c1 = cbase + tx + 16;
            float ee0 = g_ee[c0], ee1 = g_ee[c1];
            float zz0 = s_zzl[ty], zz1 = s_zzl[ty + 16];
            float d00 = __fadd_rn(__fadd_rn(zz0, -__fmul_rn(2.0f, a00)), ee0);
            float d01 = __fadd_rn(__fadd_rn(zz0, -__fmul_rn(2.0f, a01)), ee1);
            float d10 = __fadd_rn(__fadd_rn(zz1, -__fmul_rn(2.0f, a10)), ee0);
            float d11 = __fadd_rn(__fadd_rn(zz1, -__fmul_rn(2.0f, a11)), ee1);
            upd1(bv0, bi0, d00, c0); upd1(bv0, bi0, d01, c1);
            upd1(bv1, bi1, d10, c0); upd1(bv1, bi1, d11, c1);
        }
        __syncthreads();
        s_rv[ty * 16 + tx] = bv0;        s_ri[ty * 16 + tx] = bi0;
        s_rv[(ty + 16) * 16 + tx] = bv1; s_ri[(ty + 16) * 16 + tx] = bi1;
        __syncthreads();
        if (tid < 32 && tid < np) {
            float bv = s_rv[tid * 16]; int bi = s_ri[tid * 16];
#pragma unroll
            for (int k = 1; k < 16; k++)
                upd1(bv, bi, s_rv[tid * 16 + k], s_ri[tid * 16 + k]);
            int n = g_fixlist[base + tid];
            unsigned long long key =
                ((unsigned long long)__float_as_uint(bv) << 32) | (unsigned int)bi;
            atomicMin(&g_best[n], key);
        }
        __syncthreads();
    }
}

// ---------------- finalize rescued indices ----------------
__global__ __launch_bounds__(256) void k_fin(float* __restrict__ out) {
    int e = blockIdx.x * 256 + threadIdx.x;
    int cnt = min(g_fixn, NPTS);
    if (e < cnt) {
        int n = g_fixlist[e];
        int idx = (int)(unsigned int)(g_best[n] & 0xFFFFFFFFull);
        g_idx[n] = idx;
        out[OFF_IDX + n] = (float)idx;
    }
}

// ---------------- fused epilogue: gather z_q, loss, counts, embed_sum ----------------
__global__ __launch_bounds__(256)
void k_epi(const float* __restrict__ z, const float* __restrict__ E,
           float* __restrict__ out) {
    __shared__ float tile[64 * 129];
    __shared__ float lred[8];
    __shared__ int s_code[128];
    const int tid = threadIdx.x;
    const int n0 = blockIdx.x * 128;
    const int b = n0 >> 10, hw0 = n0 & 1023;
    const float* zb = z + (size_t)b * DIM * HW + hw0;
    float* ob = out + OFF_ZQ + (size_t)b * DIM * HW + hw0;
    const int w = tid >> 5, lane = tid & 31;
    float lacc = 0.f;

    if (tid < 128) s_code[tid] = g_idx[n0 + tid];

    for (int c = 0; c < 4; c++) {
#pragma unroll
        for (int r = 0; r < 32; r++) {
            int idx = tid + r * 256;
            int dd = idx >> 7, pt = idx & 127;
            tile[dd * 129 + pt] = zb[(size_t)(c * 64 + dd) * HW + pt];
        }
        __syncthreads();
        for (int q = 0; q < 16; q++) {
            int pt = w * 16 + q;
            int code = s_code[pt];
            int d = c * 64 + lane * 2;
            float2 ev = *reinterpret_cast<const float2*>(&E[(size_t)code * DIM + d]);
            float z0 = tile[(lane * 2) * 129 + pt];
            float z1 = tile[(lane * 2 + 1) * 129 + pt];
            float d0 = __fadd_rn(z0, -ev.x);
            float d1 = __fadd_rn(z1, -ev.y);
            lacc = fmaf(d0, d0, lacc);
            lacc = fmaf(d1, d1, lacc);
            float o0 = __fadd_rn(z0, __fadd_rn(ev.x, -z0));
            float o1 = __fadd_rn(z1, __fadd_rn(ev.y, -z1));
            tile[(lane * 2) * 129 + pt] = o0;
            tile[(lane * 2 + 1) * 129 + pt] = o1;
            atomicAdd(reinterpret_cast<float2*>(&g_es[(size_t)code * DIM + d]),
                      make_float2(z0, z1));
        }
        __syncthreads();
#pragma unroll
        for (int r = 0; r < 32; r++) {
            int idx = tid + r * 256;
            int dd = idx >> 7, pt = idx & 127;
            ob[(size_t)(c * 64 + dd) * HW + pt] = tile[dd * 129 + pt];
        }
        __syncthreads();
    }
    if (tid < 128) atomicAdd(&g_counts[s_code[tid]], 1.0f);
#pragma unroll
    for (int o = 16; o; o >>= 1) lacc += __shfl_xor_sync(0xffffffffu, lacc, o);
    if (!lane) lred[w] = lacc;
    __syncthreads();
    if (tid == 0) {
        float s = 0.f;
#pragma unroll
        for (int i = 0; i < 8; i++) s += lred[i];
        atomicAdd(&g_loss, s);
    }
}

// ---------------- new_cs + n + loss scalar ----------------
__global__ void k4a(const float* __restrict__ ema_cs, float* __restrict__ out) {
    __shared__ float red[32];
    int k = threadIdx.x;
    float ncs = __fadd_rn(__fmul_rn(0.99f, ema_cs[k]), __fmul_rn(0.01f, g_counts[k]));
    g_newcs[k] = ncs;
    out[OFF_CS + k] = ncs;
    float s = ncs;
#pragma unroll
    for (int o = 16; o; o >>= 1) s += __shfl_xor_sync(0xffffffffu, s, o);
    if ((k & 31) == 0) red[k >> 5] = s;
    __syncthreads();
    if (k < 32) {
        float v = red[k];
#pragma unroll
        for (int o = 16; o; o >>= 1) v += __shfl_xor_sync(0xffffffffu, v, o);
        if (!k) {
            g_nsum = v;
            out[OFF_LOSS] = g_loss * (1.0f / 8388608.0f);
        }
    }
}

// ---------------- new_es + new_embedding ----------------
__global__ void k4b(const float* __restrict__ ema_es, float* __restrict__ out) {
    int k = blockIdx.x, d = threadIdx.x;
    size_t i = (size_t)k * DIM + d;
    float es = __fadd_rn(__fmul_rn(0.99f, ema_es[i]), __fmul_rn(0.01f, g_es[i]));
    out[OFF_ES + i] = es;
    float n = g_nsum;
    float cs = __fmul_rn(__fdiv_rn(__fadd_rn(g_newcs[k], 1e-5f),
                                   __fadd_rn(n, 0.01024f)), n);
    out[OFF_EMB + i] = __fdiv_rn(es, cs);
}

extern "C" void kernel_launch(void* const* d_in, const int* in_sizes, int n_in,
                              void* d_out, int out_size) {
    const float* z      = (const float*)d_in[0];
    const float* E      = (const float*)d_in[1];
    const float* ema_cs = (const float*)d_in[2];
    const float* ema_es = (const float*)d_in[3];
    float* out = (float*)d_out;

    cudaFuncSetAttribute(k_gemm, cudaFuncAttributeMaxDynamicSharedMemorySize, SMEM_GEMM);
    cudaFuncSetAttribute(k_fix, cudaFuncAttributeMaxDynamicSharedMemorySize, SMEM_FIX);

    k_prep_a<<<256, 256>>>(E, z);                // 1: ee + zz+pack
    k_prep_bc<<<1669, 256>>>(E);                 // 2: split E + zero + g_best init
    k_gemm<<<256, 256, SMEM_GEMM>>>(z, out);     // 3: gemm + top2 + z gather
    k_fix<<<512, 256, SMEM_FIX>>>(E);            // 4  <- ncu captures this
    k_fin<<<128, 256>>>(out);                    // 5
    k_epi<<<NPTS / 128, 256>>>(z, E, out);       // 6
    k4a<<<1, 1024>>>(ema_cs, out);               // 7
    k4b<<<KCODES, DIM>>>(ema_es, out);           // 8
}

// round 16
// speedup vs baseline: 1.2183x; 1.1698x over previous
#include <cuda_runtime.h>
#include <cuda_bf16.h>
#include <math_constants.h>
#include <cstdint>

#define NPTS   32768
#define KCODES 1024
#define DIM    256
#define HW     1024

#define OFF_ZQ    0ul
#define OFF_LOSS  8388608ul
#define OFF_IDX   8388609ul
#define OFF_EMB   8421377ul
#define OFF_CS    8683521ul
#define OFF_ES    8684545ul

#define EPS_GAP 3.5e-4f

// ---------------- device scratch ----------------
__device__ float g_zz[NPTS];
__device__ float g_ee[KCODES];
__device__ int   g_idx[NPTS];
__device__ int   g_fixlist[NPTS];
__device__ int   g_fixn;
__device__ unsigned long long g_best[NPTS];
__device__ float g_es[KCODES * DIM];
__device__ float g_counts[KCODES];
__device__ float g_loss;
__device__ float g_nsum;
__device__ float g_newcs[KCODES];

// compacted flagged points: z rows + zz, indexed by fixlist position
__device__ float g_zfix[NPTS * DIM];
__device__ float g_zzfix[NPTS];

// packed bf16 pairs
__device__ uint32_t g_zp[128 * NPTS];
__device__ uint32_t g_ep[128 * KCODES];

// ---------------- helpers ----------------
__device__ __forceinline__ uint32_t smem_u32(const void* p) {
    uint32_t a;
    asm("{ .reg .u64 t; cvta.to.shared.u64 t, %1; cvt.u32.u64 %0, t; }" : "=r"(a) : "l"(p));
    return a;
}
__device__ __forceinline__ uint32_t pack_bf16(float lo, float hi) {
    __nv_bfloat162 t = __floats2bfloat162_rn(lo, hi);
    return *reinterpret_cast<uint32_t*>(&t);
}
__device__ __forceinline__ void cp16(uint32_t dst, const void* src) {
    asm volatile("cp.async.cg.shared.global [%0], [%1], 16;" :: "r"(dst), "l"(src));
}
#define CP_COMMIT() asm volatile("cp.async.commit_group;" ::: "memory")
#define CP_WAIT1()  asm volatile("cp.async.wait_group 1;" ::: "memory")
#define CP_WAIT0()  asm volatile("cp.async.wait_group 0;" ::: "memory")

__device__ __forceinline__ void mma16(float* c, const uint32_t* a, uint32_t b0, uint32_t b1) {
    asm volatile(
        "mma.sync.aligned.m16n8k16.row.col.f32.bf16.bf16.f32 "
        "{%0,%1,%2,%3}, {%4,%5,%6,%7}, {%8,%9}, {%0,%1,%2,%3};"
        : "+f"(c[0]), "+f"(c[1]), "+f"(c[2]), "+f"(c[3])
        : "r"(a[0]), "r"(a[1]), "r"(a[2]), "r"(a[3]), "r"(b0), "r"(b1));
}

// top-2 insert, jnp.argmin tie-break
__device__ __forceinline__ void ins2(float& b0v, int& b0i, float& b1v, int& b1i,
                                     float v, int ix) {
    if (v < b0v || (v == b0v && ix < b0i)) {
        b1v = b0v; b1i = b0i; b0v = v; b0i = ix;
    } else if (v < b1v || (v == b1v && ix < b1i)) {
        b1v = v; b1i = ix;
    }
}
__device__ __forceinline__ void upd1(float& bv, int& bi, float v, int ix) {
    if (v < bv || (v == bv && ix < bi)) { bv = v; bi = ix; }
}

// ---------------- merged prep: ee | zz+pack | split E | zero | g_best init ----------------
// blocks: [0,128) ee ; [128,256) zz+pack ; [256,768) splitE ; [768,1797) zero ; [1797,1925) best
#define PREP_BLOCKS 1925
__global__ __launch_bounds__(256) void k_prep(const float* __restrict__ E,
                                              const float* __restrict__ z) {
    int bid = blockIdx.x, tid = threadIdx.x;
    if (bid < 128) {
        int w = bid * 8 + (tid >> 5);
        int lane = tid & 31;
        const float* row = E + (size_t)w * DIM;
        float s = 0.f;
#pragma unroll
        for (int i = 0; i < 8; i++) { float v = row[lane + i * 32]; s = fmaf(v, v, s); }
#pragma unroll
        for (int o = 16; o; o >>= 1) s += __shfl_xor_sync(0xffffffffu, s, o);
        if (!lane) g_ee[w] = s;
    } else if (bid < 256) {
        int n = (bid - 128) * 256 + tid;
        int b = n >> 10, hw = n & 1023;
        const float* p = z + (size_t)b * DIM * HW + hw;
        float s = 0.f;
#pragma unroll 4
        for (int k2 = 0; k2 < 128; k2++) {
            float v0 = p[(size_t)(2 * k2) * HW];
            float v1 = p[(size_t)(2 * k2 + 1) * HW];
            s = fmaf(v0, v0, s);
            s = fmaf(v1, v1, s);
            g_zp[(size_t)k2 * NPTS + n] = pack_bf16(v0, v1);
        }
        g_zz[n] = s;
    } else if (bid < 768) {
        int i = (bid - 256) * 256 + tid;
        int code = i >> 7, k2 = i & 127;
        float v0 = E[(size_t)code * 256 + 2 * k2];
        float v1 = E[(size_t)code * 256 + 2 * k2 + 1];
        g_ep[k2 * KCODES + code] = pack_bf16(v0, v1);
    } else if (bid < 1797) {
        int i = (bid - 768) * 256 + tid;
        if (i < KCODES * DIM) g_es[i] = 0.f;
        else if (i < KCODES * DIM + KCODES) g_counts[i - KCODES * DIM] = 0.f;
        else if (i == KCODES * DIM + KCODES) g_loss = 0.f;
        else if (i == KCODES * DIM + KCODES + 1) g_nsum = 0.f;
        else if (i == KCODES * DIM + KCODES + 2) g_fixn = 0;
    } else {
        int i = (bid - 1797) * 256 + tid;
        g_best[i] = 0xFFFFFFFFFFFFFFFFull;
    }
}

// ---------------- single-pass bf16 mma GEMM + top-2 argmin + z gather ----------------
#define APITCH  136
#define BPITCH  136
#define SM_ZZ   0
#define SM_EE   512
#define SM_RED  4608
#define SM_A    8704
#define SM_B    (SM_A + 128 * APITCH * 4)
#define BSTAGE  (16 * BPITCH * 4)
#define SMEM_GEMM (SM_B + 3 * BSTAGE)

__device__ __forceinline__ void load_b_stage(uint32_t dstb, int g, int tid) {
    int nt1 = g >> 3, kc1 = g & 7;
    const uint32_t* ep = g_ep + (size_t)kc1 * 16 * KCODES + nt1 * 128;
#pragma unroll
    for (int j = 0; j < 2; j++) {
        int idx = tid + j * 256;
        int r = idx >> 5, cc = idx & 31;
        cp16(dstb + r * (BPITCH * 4) + cc * 16, ep + (size_t)r * KCODES + cc * 4);
    }
}

__global__ __launch_bounds__(256, 2) void k_gemm(const float* __restrict__ z,
                                                 float* __restrict__ out) {
    extern __shared__ uint8_t smem[];
    __shared__ int s_fN[128];
    __shared__ int s_fP[128];
    __shared__ int s_fcnt;
    uint32_t sb = smem_u32(smem);
    float* s_zz = reinterpret_cast<float*>(smem + SM_ZZ);
    float* s_ee = reinterpret_cast<float*>(smem + SM_EE);
    float* sB0v = reinterpret_cast<float*>(smem + SM_RED);
    int*   sB0i = reinterpret_cast<int*>(smem + SM_RED + 1024);
    float* sB1v = reinterpret_cast<float*>(smem + SM_RED + 2048);
    int*   sB1i = reinterpret_cast<int*>(smem + SM_RED + 3072);
    const uint32_t* sA = reinterpret_cast<const uint32_t*>(smem + SM_A);

    const int tid = threadIdx.x, cid = blockIdx.x;
    const int lane = tid & 31, w = tid >> 5;
    const int gq = lane >> 2, tig = lane & 3;
    const int mw = (w >> 1) * 32, nw = (w & 1) * 64;

    if (tid == 0) s_fcnt = 0;
    if (tid < 128) s_zz[tid] = g_zz[cid * 128 + tid];
#pragma unroll
    for (int i = 0; i < 4; i++) s_ee[tid + 256 * i] = g_ee[tid + 256 * i];

    {
        const uint32_t* zp = g_zp + (size_t)cid * 128;
#pragma unroll
        for (int j = 0; j < 16; j++) {
            int idx = tid + j * 256;
            int r = idx >> 5, cc = idx & 31;
            cp16(sb + SM_A + r * (APITCH * 4) + cc * 16, zp + (size_t)r * NPTS + cc * 4);
        }
    }
    load_b_stage(sb + SM_B, 0, tid);
    CP_COMMIT();
    load_b_stage(sb + SM_B + BSTAGE, 1, tid);
    CP_COMMIT();

    float acc[2][8][4];
#pragma unroll
    for (int mt = 0; mt < 2; mt++)
#pragma unroll
        for (int nt = 0; nt < 8; nt++)
#pragma unroll
            for (int q = 0; q < 4; q++) acc[mt][nt][q] = 0.f;
    float b0v[4], b1v[4]; int b0i[4], b1i[4];
#pragma unroll
    for (int i = 0; i < 4; i++) {
        b0v[i] = CUDART_INF_F; b0i[i] = 0x7fffffff;
        b1v[i] = CUDART_INF_F; b1i[i] = 0x7fffffff;
    }
    __syncthreads();
    float zzv[4];
#pragma unroll
    for (int mt = 0; mt < 2; mt++) {
        zzv[mt * 2]     = s_zz[mw + mt * 16 + gq];
        zzv[mt * 2 + 1] = s_zz[mw + mt * 16 + gq + 8];
    }

    int stage = 0;
    for (int it = 0; it < 64; it++) {
        if (it < 63) { CP_WAIT1(); } else { CP_WAIT0(); }
        __syncthreads();
        if (it + 2 < 64) {
            int st2 = stage + 2; if (st2 >= 3) st2 -= 3;
            load_b_stage(sb + SM_B + st2 * BSTAGE, it + 2, tid);
            CP_COMMIT();
        }

        const int kc = it & 7;
        const uint32_t* B = reinterpret_cast<const uint32_t*>(smem + SM_B + stage * BSTAGE);
        const uint32_t* Achunk = sA + (kc * 16) * APITCH;

#pragma unroll
        for (int ks = 0; ks < 2; ks++) {
            const int kb = ks * 8;
            uint32_t af[2][4];
#pragma unroll
            for (int mt = 0; mt < 2; mt++) {
                const uint32_t* Ap = Achunk + (kb + tig) * APITCH + mw + mt * 16 + gq;
                af[mt][0] = Ap[0];
                af[mt][1] = Ap[8];
                const uint32_t* Ap2 = Achunk + (kb + 4 + tig) * APITCH + mw + mt * 16 + gq;
                af[mt][2] = Ap2[0];
                af[mt][3] = Ap2[8];
            }
#pragma unroll
            for (int nt = 0; nt < 8; nt++) {
                uint32_t bf0 = B[(kb + tig) * BPITCH + nw + nt * 8 + gq];
                uint32_t bf1 = B[(kb + 4 + tig) * BPITCH + nw + nt * 8 + gq];
#pragma unroll
                for (int mt = 0; mt < 2; mt++) mma16(acc[mt][nt], af[mt], bf0, bf1);
            }
        }

        if (kc == 7) {
            int kt = it >> 3;
#pragma unroll
            for (int nt = 0; nt < 8; nt++) {
                int code0 = kt * 128 + nw + nt * 8 + 2 * tig;
                float2 ee2 = *reinterpret_cast<const float2*>(&s_ee[code0]);
#pragma unroll
                for (int mt = 0; mt < 2; mt++) {
                    float d0 = __fadd_rn(__fadd_rn(zzv[mt * 2], -__fmul_rn(2.0f, acc[mt][nt][0])), ee2.x);
                    float d1 = __fadd_rn(__fadd_rn(zzv[mt * 2], -__fmul_rn(2.0f, acc[mt][nt][1])), ee2.y);
                    float d2 = __fadd_rn(__fadd_rn(zzv[mt * 2 + 1], -__fmul_rn(2.0f, acc[mt][nt][2])), ee2.x);
                    float d3 = __fadd_rn(__fadd_rn(zzv[mt * 2 + 1], -__fmul_rn(2.0f, acc[mt][nt][3])), ee2.y);
                    int r0 = mt * 2, r1 = mt * 2 + 1;
                    ins2(b0v[r0], b0i[r0], b1v[r0], b1i[r0], d0, code0);
                    ins2(b0v[r0], b0i[r0], b1v[r0], b1i[r0], d1, code0 + 1);
                    ins2(b0v[r1], b0i[r1], b1v[r1], b1i[r1], d2, code0);
                    ins2(b0v[r1], b0i[r1], b1v[r1], b1i[r1], d3, code0 + 1);
                    acc[mt][nt][0] = 0.f; acc[mt][nt][1] = 0.f;
                    acc[mt][nt][2] = 0.f; acc[mt][nt][3] = 0.f;
                }
            }
        }
        stage++; if (stage == 3) stage = 0;
    }

    __syncthreads();
#pragma unroll
    for (int i = 0; i < 4; i++) {
        float v0 = b0v[i], v1 = b1v[i]; int i0 = b0i[i], i1 = b1i[i];
#pragma unroll
        for (int o = 1; o <= 2; o <<= 1) {
            float ov0 = __shfl_xor_sync(0xffffffffu, v0, o);
            int   oi0 = __shfl_xor_sync(0xffffffffu, i0, o);
            float ov1 = __shfl_xor_sync(0xffffffffu, v1, o);
            int   oi1 = __shfl_xor_sync(0xffffffffu, i1, o);
            ins2(v0, i0, v1, i1, ov0, oi0);
            ins2(v0, i0, v1, i1, ov1, oi1);
        }
        if (tig == 0) {
            int row = mw + (i >> 1) * 16 + gq + (i & 1) * 8;
            int half = (w & 1) * 128;
            sB0v[half + row] = v0; sB0i[half + row] = i0;
            sB1v[half + row] = v1; sB1i[half + row] = i1;
        }
    }
    __syncthreads();
    if (tid < 128) {
        float v0 = sB0v[tid], v1 = sB1v[tid];
        int i0 = sB0i[tid], i1 = sB1i[tid];
        ins2(v0, i0, v1, i1, sB0v[128 + tid], sB0i[128 + tid]);
        ins2(v0, i0, v1, i1, sB1v[128 + tid], sB1i[128 + tid]);
        int n = cid * 128 + tid;
        g_idx[n] = i0;
        out[OFF_IDX + n] = (float)i0;
        if (__fadd_rn(v1, -v0) < EPS_GAP) {
            int pos = atomicAdd(&g_fixn, 1);
            if (pos < NPTS) {
                g_fixlist[pos] = n;
                int l = atomicAdd(&s_fcnt, 1);
                s_fN[l] = n; s_fP[l] = pos;
            }
        }
    }
    // ---- gather flagged z rows into compacted g_zfix (coalesced consumer reads) ----
    __syncthreads();
    int fc = s_fcnt;
    for (int e = 0; e < fc; e++) {
        int n2 = s_fN[e], pos2 = s_fP[e];
        int b2 = n2 >> 10, hw2 = n2 & 1023;
        g_zfix[(size_t)pos2 * DIM + tid] = z[((size_t)b2 * DIM + tid) * HW + hw2];
        if (tid == 0) g_zzfix[pos2] = g_zz[n2];
    }
}

// ---------------- rescue v7: exact fp32 scan, 4pts x 2codes, shuffle reduce ----------------
// item = (32 pts x 64 codes), 16-way code split. warp = fixed ty -> z reads broadcast.
// z [pt][FROW=65] float4 ; e [k4][EROW=65] float4 (64 codes per row, conflict-free reads)
#define FROW 65
#define EROW 65
#define SMFX_E  (32 * FROW * 16)                    // 33280
#define SMFX_ZZ (SMFX_E + 64 * EROW * 16)           // 99840
#define SMEM_FIX (SMFX_ZZ + 128)                    // 99968
__global__ __launch_bounds__(256) void k_fix(const float* __restrict__ E) {
    extern __shared__ uint8_t sm[];
    float4* s_z4 = reinterpret_cast<float4*>(sm);              // [32][FROW]
    float4* s_e4 = reinterpret_cast<float4*>(sm + SMFX_E);     // [64][EROW]
    float*  s_zzl = reinterpret_cast<float*>(sm + SMFX_ZZ);

    const int tid = threadIdx.x;
    const int tx = tid & 31, ty = tid >> 5;    // warp = fixed ty
    int cnt = min(g_fixn, NPTS);
    int nwork = ((cnt + 31) >> 5) * 16;

    for (int wi = blockIdx.x; wi < nwork; wi += gridDim.x) {
        int g = wi >> 4, seg = wi & 15;
        int base = g * 32;
        int np = min(32, cnt - base);
        // ---- fill z tile: coalesced from g_zfix ----
        {
            const float4* zf4 = reinterpret_cast<const float4*>(g_zfix);
#pragma unroll
            for (int j = 0; j < 8; j++) {
                int idx = tid + j * 256;
                int row = idx >> 6, c4 = idx & 63;
                int rl = (row < np) ? row : 0;
                s_z4[row * FROW + c4] = zf4[(size_t)(base + rl) * 64 + c4];
            }
            if (tid < 32) {
                int rl = (tid < np) ? tid : 0;
                s_zzl[tid] = g_zzfix[base + rl];
            }
        }
        // ---- fill e tile: 64 codes x 64 k4, k4-major ----
        {
            int cbase = seg * 64;
            const float4* E4 = reinterpret_cast<const float4*>(E) + (size_t)cbase * 64;
#pragma unroll
            for (int j = 0; j < 16; j++) {
                int idx = tid + j * 256;
                int c = idx >> 6, k4 = idx & 63;
                s_e4[k4 * EROW + c] = E4[c * 64 + k4];
            }
        }
        __syncthreads();

        int cbase = seg * 64;
        float a[4][2];
#pragma unroll
        for (int p = 0; p < 4; p++) { a[p][0] = 0.f; a[p][1] = 0.f; }
#pragma unroll 8
        for (int k4 = 0; k4 < 64; k4++) {
            float4 e0 = s_e4[k4 * EROW + tx];
            float4 e1 = s_e4[k4 * EROW + tx + 32];
#pragma unroll
            for (int p = 0; p < 4; p++) {
                float4 zv = s_z4[(ty + 8 * p) * FROW + k4];
                a[p][0] = fmaf(zv.x, e0.x, a[p][0]); a[p][0] = fmaf(zv.y, e0.y, a[p][0]);
                a[p][0] = fmaf(zv.z, e0.z, a[p][0]); a[p][0] = fmaf(zv.w, e0.w, a[p][0]);
                a[p][1] = fmaf(zv.x, e1.x, a[p][1]); a[p][1] = fmaf(zv.y, e1.y, a[p][1]);
                a[p][1] = fmaf(zv.z, e1.z, a[p][1]); a[p][1] = fmaf(zv.w, e1.w, a[p][1]);
            }
        }
        int c0 = cbase + tx, c1 = cbase + tx + 32;
        float ee0 = g_ee[c0], ee1 = g_ee[c1];
#pragma unroll
        for (int p = 0; p < 4; p++) {
            float zzp = s_zzl[ty + 8 * p];
            float d0 = __fadd_rn(__fadd_rn(zzp, -__fmul_rn(2.0f, a[p][0])), ee0);
            float d1 = __fadd_rn(__fadd_rn(zzp, -__fmul_rn(2.0f, a[p][1])), ee1);
            float bv; int bi;
            if (d0 < d1 || (d0 == d1 && c0 < c1)) { bv = d0; bi = c0; }
            else { bv = d1; bi = c1; }
            // warp butterfly top-1 (tie -> lowest index)
#pragma unroll
            for (int o = 16; o; o >>= 1) {
                float ov = __shfl_xor_sync(0xffffffffu, bv, o);
                int oi = __shfl_xor_sync(0xffffffffu, bi, o);
                upd1(bv, bi, ov, oi);
            }
            if (tx == 0) {
                int row = ty + 8 * p;
                if (row < np) {
                    int n = g_fixlist[base + row];
                    unsigned long long key =
                        ((unsigned long long)__float_as_uint(bv) << 32) | (unsigned int)bi;
                    atomicMin(&g_best[n], key);
                }
            }
        }
        __syncthreads();
    }
}

// ---------------- fused epilogue (+ rescued-index finalize): z_q, loss, counts, es ----------------
__global__ __launch_bounds__(256)
void k_epi(const float* __restrict__ z, const float* __restrict__ E,
           float* __restrict__ out) {
    __shared__ float tile[64 * 129];
    __shared__ float lred[8];
    __shared__ int s_code[128];
    const int tid = threadIdx.x;
    const int n0 = blockIdx.x * 128;
    const int b = n0 >> 10, hw0 = n0 & 1023;
    const float* zb = z + (size_t)b * DIM * HW + hw0;
    float* ob = out + OFF_ZQ + (size_t)b * DIM * HW + hw0;
    const int w = tid >> 5, lane = tid & 31;
    float lacc = 0.f;

    if (tid < 128) {
        int n = n0 + tid;
        unsigned long long bst = g_best[n];
        int code = (bst != 0xFFFFFFFFFFFFFFFFull)
                       ? (int)(unsigned int)(bst & 0xFFFFFFFFull)
                       : g_idx[n];
        s_code[tid] = code;
        out[OFF_IDX + n] = (float)code;
    }

    for (int c = 0; c < 4; c++) {
#pragma unroll
        for (int r = 0; r < 32; r++) {
            int idx = tid + r * 256;
            int dd = idx >> 7, pt = idx & 127;
            tile[dd * 129 + pt] = zb[(size_t)(c * 64 + dd) * HW + pt];
        }
        __syncthreads();
        for (int q = 0; q < 16; q++) {
            int pt = w * 16 + q;
            int code = s_code[pt];
            int d = c * 64 + lane * 2;
            float2 ev = *reinterpret_cast<const float2*>(&E[(size_t)code * DIM + d]);
            float z0 = tile[(lane * 2) * 129 + pt];
            float z1 = tile[(lane * 2 + 1) * 129 + pt];
            float d0 = __fadd_rn(z0, -ev.x);
            float d1 = __fadd_rn(z1, -ev.y);
            lacc = fmaf(d0, d0, lacc);
            lacc = fmaf(d1, d1, lacc);
            float o0 = __fadd_rn(z0, __fadd_rn(ev.x, -z0));
            float o1 = __fadd_rn(z1, __fadd_rn(ev.y, -z1));
            tile[(lane * 2) * 129 + pt] = o0;
            tile[(lane * 2 + 1) * 129 + pt] = o1;
            atomicAdd(reinterpret_cast<float2*>(&g_es[(size_t)code * DIM + d]),
                      make_float2(z0, z1));
        }
        __syncthreads();
#pragma unroll
        for (int r = 0; r < 32; r++) {
            int idx = tid + r * 256;
            int dd = idx >> 7, pt = idx & 127;
            ob[(size_t)(c * 64 + dd) * HW + pt] = tile[dd * 129 + pt];
        }
        __syncthreads();
    }
    if (tid < 128) atomicAdd(&g_counts[s_code[tid]], 1.0f);
#pragma unroll
    for (int o = 16; o; o >>= 1) lacc += __shfl_xor_sync(0xffffffffu, lacc, o);
    if (!lane) lred[w] = lacc;
    __syncthreads();
    if (tid == 0) {
        float s = 0.f;
#pragma unroll
        for (int i = 0; i < 8; i++) s += lred[i];
        atomicAdd(&g_loss, s);
    }
}

// ---------------- new_cs + n + loss scalar ----------------
__global__ void k4a(const float* __restrict__ ema_cs, float* __restrict__ out) {
    __shared__ float red[32];
    int k = threadIdx.x;
    float ncs = __fadd_rn(__fmul_rn(0.99f, ema_cs[k]), __fmul_rn(0.01f, g_counts[k]));
    g_newcs[k] = ncs;
    out[OFF_CS + k] = ncs;
    float s = ncs;
#pragma unroll
    for (int o = 16; o; o >>= 1) s += __shfl_xor_sync(0xffffffffu, s, o);
    if ((k & 31) == 0) red[k >> 5] = s;
    __syncthreads();
    if (k < 32) {
        float v = red[k];
#pragma unroll
        for (int o = 16; o; o >>= 1) v += __shfl_xor_sync(0xffffffffu, v, o);
        if (!k) {
            g_nsum = v;
            out[OFF_LOSS] = g_loss * (1.0f / 8388608.0f);
        }
    }
}

// ---------------- new_es + new_embedding ----------------
__global__ void k4b(const float* __restrict__ ema_es, float* __restrict__ out) {
    int k = blockIdx.x, d = threadIdx.x;
    size_t i = (size_t)k * DIM + d;
    float es = __fadd_rn(__fmul_rn(0.99f, ema_es[i]), __fmul_rn(0.01f, g_es[i]));
    out[OFF_ES + i] = es;
    float n = g_nsum;
    float cs = __fmul_rn(__fdiv_rn(__fadd_rn(g_newcs[k], 1e-5f),
                                   __fadd_rn(n, 0.01024f)), n);
    out[OFF_EMB + i] = __fdiv_rn(es, cs);
}

extern "C" void kernel_launch(void* const* d_in, const int* in_sizes, int n_in,
                              void* d_out, int out_size) {
    const float* z      = (const float*)d_in[0];
    const float* E      = (const float*)d_in[1];
    const float* ema_cs = (const float*)d_in[2];
    const float* ema_es = (const float*)d_in[3];
    float* out = (float*)d_out;

    cudaFuncSetAttribute(k_gemm, cudaFuncAttributeMaxDynamicSharedMemorySize, SMEM_GEMM);
    cudaFuncSetAttribute(k_fix, cudaFuncAttributeMaxDynamicSharedMemorySize, SMEM_FIX);

    k_prep<<<PREP_BLOCKS, 256>>>(E, z);          // 1: all prep
    k_gemm<<<256, 256, SMEM_GEMM>>>(z, out);     // 2: gemm + top2 + z gather
    k_fix<<<296, 256, SMEM_FIX>>>(E);            // 3: rescue (2 CTA/SM, one wave)
    k_epi<<<NPTS / 128, 256>>>(z, E, out);       // 4  <- ncu captures this
    k4a<<<1, 1024>>>(ema_cs, out);               // 5
    k4b<<<KCODES, DIM>>>(ema_es, out);           // 6
}

// round 17
// speedup vs baseline: 1.2223x; 1.0033x over previous
#include <cuda_runtime.h>
#include <cuda_bf16.h>
#include <math_constants.h>
#include <cstdint>

#define NPTS   32768
#define KCODES 1024
#define DIM    256
#define HW     1024

#define OFF_ZQ    0ul
#define OFF_LOSS  8388608ul
#define OFF_IDX   8388609ul
#define OFF_EMB   8421377ul
#define OFF_CS    8683521ul
#define OFF_ES    8684545ul

#define EPS_GAP 3.5e-4f

// ---------------- device scratch ----------------
__device__ float g_zz[NPTS];
__device__ float g_ee[KCODES];
__device__ int   g_idx[NPTS];
__device__ int   g_fixlist[NPTS];
__device__ int   g_fixn;
__device__ unsigned long long g_best[NPTS];
__device__ float g_es[KCODES * DIM];
__device__ float g_counts[KCODES];
__device__ float g_loss;
__device__ float g_nsum;
__device__ float g_newcs[KCODES];

// compacted flagged points: z rows + zz, indexed by fixlist position
__device__ float g_zfix[NPTS * DIM];
__device__ float g_zzfix[NPTS];

// packed bf16 pairs
__device__ uint32_t g_zp[128 * NPTS];
__device__ uint32_t g_ep[128 * KCODES];

// ---------------- helpers ----------------
__device__ __forceinline__ uint32_t smem_u32(const void* p) {
    uint32_t a;
    asm("{ .reg .u64 t; cvta.to.shared.u64 t, %1; cvt.u32.u64 %0, t; }" : "=r"(a) : "l"(p));
    return a;
}
__device__ __forceinline__ uint32_t pack_bf16(float lo, float hi) {
    __nv_bfloat162 t = __floats2bfloat162_rn(lo, hi);
    return *reinterpret_cast<uint32_t*>(&t);
}
__device__ __forceinline__ void cp16(uint32_t dst, const void* src) {
    asm volatile("cp.async.cg.shared.global [%0], [%1], 16;" :: "r"(dst), "l"(src));
}
#define CP_COMMIT() asm volatile("cp.async.commit_group;" ::: "memory")
#define CP_WAIT0()  asm volatile("cp.async.wait_group 0;" ::: "memory")

__device__ __forceinline__ void mma16(float* c, const uint32_t* a, uint32_t b0, uint32_t b1) {
    asm volatile(
        "mma.sync.aligned.m16n8k16.row.col.f32.bf16.bf16.f32 "
        "{%0,%1,%2,%3}, {%4,%5,%6,%7}, {%8,%9}, {%0,%1,%2,%3};"
        : "+f"(c[0]), "+f"(c[1]), "+f"(c[2]), "+f"(c[3])
        : "r"(a[0]), "r"(a[1]), "r"(a[2]), "r"(a[3]), "r"(b0), "r"(b1));
}

// top-2 insert, jnp.argmin tie-break
__device__ __forceinline__ void ins2(float& b0v, int& b0i, float& b1v, int& b1i,
                                     float v, int ix) {
    if (v < b0v || (v == b0v && ix < b0i)) {
        b1v = b0v; b1i = b0i; b0v = v; b0i = ix;
    } else if (v < b1v || (v == b1v && ix < b1i)) {
        b1v = v; b1i = ix;
    }
}
__device__ __forceinline__ void upd1(float& bv, int& bi, float v, int ix) {
    if (v < bv || (v == bv && ix < bi)) { bv = v; bi = ix; }
}

// ---------------- merged prep: ee | zz+pack | split E | zero | g_best init ----------------
#define PREP_BLOCKS 1925
__global__ __launch_bounds__(256) void k_prep(const float* __restrict__ E,
                                              const float* __restrict__ z) {
    int bid = blockIdx.x, tid = threadIdx.x;
    if (bid < 128) {
        int w = bid * 8 + (tid >> 5);
        int lane = tid & 31;
        const float* row = E + (size_t)w * DIM;
        float s = 0.f;
#pragma unroll
        for (int i = 0; i < 8; i++) { float v = row[lane + i * 32]; s = fmaf(v, v, s); }
#pragma unroll
        for (int o = 16; o; o >>= 1) s += __shfl_xor_sync(0xffffffffu, s, o);
        if (!lane) g_ee[w] = s;
    } else if (bid < 256) {
        int n = (bid - 128) * 256 + tid;
        int b = n >> 10, hw = n & 1023;
        const float* p = z + (size_t)b * DIM * HW + hw;
        float s = 0.f;
#pragma unroll 4
        for (int k2 = 0; k2 < 128; k2++) {
            float v0 = p[(size_t)(2 * k2) * HW];
            float v1 = p[(size_t)(2 * k2 + 1) * HW];
            s = fmaf(v0, v0, s);
            s = fmaf(v1, v1, s);
            g_zp[(size_t)k2 * NPTS + n] = pack_bf16(v0, v1);
        }
        g_zz[n] = s;
    } else if (bid < 768) {
        int i = (bid - 256) * 256 + tid;
        int code = i >> 7, k2 = i & 127;
        float v0 = E[(size_t)code * 256 + 2 * k2];
        float v1 = E[(size_t)code * 256 + 2 * k2 + 1];
        g_ep[k2 * KCODES + code] = pack_bf16(v0, v1);
    } else if (bid < 1797) {
        int i = (bid - 768) * 256 + tid;
        if (i < KCODES * DIM) g_es[i] = 0.f;
        else if (i < KCODES * DIM + KCODES) g_counts[i - KCODES * DIM] = 0.f;
        else if (i == KCODES * DIM + KCODES) g_loss = 0.f;
        else if (i == KCODES * DIM + KCODES + 1) g_nsum = 0.f;
        else if (i == KCODES * DIM + KCODES + 2) g_fixn = 0;
    } else {
        int i = (bid - 1797) * 256 + tid;
        g_best[i] = 0xFFFFFFFFFFFFFFFFull;
    }
}

// ---------------- single-pass bf16 mma GEMM + top-2 argmin + z gather ----------------
// 4-stage B buffer, 2 k-chunks per iteration, one barrier per iteration (32 total).
#define APITCH  136
#define BPITCH  136
#define SM_ZZ   0
#define SM_EE   512
#define SM_RED  4608
#define SM_A    8704
#define SM_B    (SM_A + 128 * APITCH * 4)
#define BSTAGE  (16 * BPITCH * 4)
#define SMEM_GEMM (SM_B + 4 * BSTAGE)               // 113152 (2 CTAs/SM: 226304 < 233472)

__device__ __forceinline__ void load_b_stage(uint32_t dstb, int g, int tid) {
    int nt1 = g >> 3, kc1 = g & 7;
    const uint32_t* ep = g_ep + (size_t)kc1 * 16 * KCODES + nt1 * 128;
#pragma unroll
    for (int j = 0; j < 2; j++) {
        int idx = tid + j * 256;
        int r = idx >> 5, cc = idx & 31;
        cp16(dstb + r * (BPITCH * 4) + cc * 16, ep + (size_t)r * KCODES + cc * 4);
    }
}

__global__ __launch_bounds__(256, 2) void k_gemm(const float* __restrict__ z,
                                                 float* __restrict__ out) {
    extern __shared__ uint8_t smem[];
    __shared__ int s_fN[128];
    __shared__ int s_fP[128];
    __shared__ int s_fcnt;
    uint32_t sb = smem_u32(smem);
    float* s_zz = reinterpret_cast<float*>(smem + SM_ZZ);
    float* s_ee = reinterpret_cast<float*>(smem + SM_EE);
    float* sB0v = reinterpret_cast<float*>(smem + SM_RED);
    int*   sB0i = reinterpret_cast<int*>(smem + SM_RED + 1024);
    float* sB1v = reinterpret_cast<float*>(smem + SM_RED + 2048);
    int*   sB1i = reinterpret_cast<int*>(smem + SM_RED + 3072);
    const uint32_t* sA = reinterpret_cast<const uint32_t*>(smem + SM_A);

    const int tid = threadIdx.x, cid = blockIdx.x;
    const int lane = tid & 31, w = tid >> 5;
    const int gq = lane >> 2, tig = lane & 3;
    const int mw = (w >> 1) * 32, nw = (w & 1) * 64;

    if (tid == 0) s_fcnt = 0;
    if (tid < 128) s_zz[tid] = g_zz[cid * 128 + tid];
#pragma unroll
    for (int i = 0; i < 4; i++) s_ee[tid + 256 * i] = g_ee[tid + 256 * i];

    {
        const uint32_t* zp = g_zp + (size_t)cid * 128;
#pragma unroll
        for (int j = 0; j < 16; j++) {
            int idx = tid + j * 256;
            int r = idx >> 5, cc = idx & 31;
            cp16(sb + SM_A + r * (APITCH * 4) + cc * 16, zp + (size_t)r * NPTS + cc * 4);
        }
    }
    // prologue: stages 0,1 <- chunks 0,1 (A rides with chunk-0's group)
    load_b_stage(sb + SM_B, 0, tid);
    CP_COMMIT();
    load_b_stage(sb + SM_B + BSTAGE, 1, tid);
    CP_COMMIT();

    float acc[2][8][4];
#pragma unroll
    for (int mt = 0; mt < 2; mt++)
#pragma unroll
        for (int nt = 0; nt < 8; nt++)
#pragma unroll
            for (int q = 0; q < 4; q++) acc[mt][nt][q] = 0.f;
    float b0v[4], b1v[4]; int b0i[4], b1i[4];
#pragma unroll
    for (int i = 0; i < 4; i++) {
        b0v[i] = CUDART_INF_F; b0i[i] = 0x7fffffff;
        b1v[i] = CUDART_INF_F; b1i[i] = 0x7fffffff;
    }
    __syncthreads();
    float zzv[4];
#pragma unroll
    for (int mt = 0; mt < 2; mt++) {
        zzv[mt * 2]     = s_zz[mw + mt * 16 + gq];
        zzv[mt * 2 + 1] = s_zz[mw + mt * 16 + gq + 8];
    }

    for (int it = 0; it < 32; it++) {
        const int g0 = 2 * it, g1 = 2 * it + 1;
        CP_WAIT0();                 // chunks g0,g1 resident
        __syncthreads();            // visible to all; stages (g0+2)&3,(g1+2)&3 free
        if (it + 1 < 32) {
            load_b_stage(sb + SM_B + ((g0 + 2) & 3) * BSTAGE, g0 + 2, tid);
            CP_COMMIT();
            load_b_stage(sb + SM_B + ((g1 + 2) & 3) * BSTAGE, g1 + 2, tid);
            CP_COMMIT();
        }

#pragma unroll
        for (int half = 0; half < 2; half++) {
            const int g = 2 * it + half;
            const int kc = g & 7;
            const uint32_t* B = reinterpret_cast<const uint32_t*>(
                smem + SM_B + (g & 3) * BSTAGE);
            const uint32_t* Achunk = sA + (kc * 16) * APITCH;

#pragma unroll
            for (int ks = 0; ks < 2; ks++) {
                const int kb = ks * 8;
                uint32_t af[2][4];
#pragma unroll
                for (int mt = 0; mt < 2; mt++) {
                    const uint32_t* Ap = Achunk + (kb + tig) * APITCH + mw + mt * 16 + gq;
                    af[mt][0] = Ap[0];
                    af[mt][1] = Ap[8];
                    const uint32_t* Ap2 = Achunk + (kb + 4 + tig) * APITCH + mw + mt * 16 + gq;
                    af[mt][2] = Ap2[0];
                    af[mt][3] = Ap2[8];
                }
#pragma unroll
                for (int nt = 0; nt < 8; nt++) {
                    uint32_t bf0 = B[(kb + tig) * BPITCH + nw + nt * 8 + gq];
                    uint32_t bf1 = B[(kb + 4 + tig) * BPITCH + nw + nt * 8 + gq];
#pragma unroll
                    for (int mt = 0; mt < 2; mt++) mma16(acc[mt][nt], af[mt], bf0, bf1);
                }
            }
        }

        if ((g1 & 7) == 7) {        // full K accumulated for this code supertile
            int kt = g1 >> 3;
#pragma unroll
            for (int nt = 0; nt < 8; nt++) {
                int code0 = kt * 128 + nw + nt * 8 + 2 * tig;
                float2 ee2 = *reinterpret_cast<const float2*>(&s_ee[code0]);
#pragma unroll
                for (int mt = 0; mt < 2; mt++) {
                    float d0 = __fadd_rn(__fadd_rn(zzv[mt * 2], -__fmul_rn(2.0f, acc[mt][nt][0])), ee2.x);
                    float d1 = __fadd_rn(__fadd_rn(zzv[mt * 2], -__fmul_rn(2.0f, acc[mt][nt][1])), ee2.y);
                    float d2 = __fadd_rn(__fadd_rn(zzv[mt * 2 + 1], -__fmul_rn(2.0f, acc[mt][nt][2])), ee2.x);
                    float d3 = __fadd_rn(__fadd_rn(zzv[mt * 2 + 1], -__fmul_rn(2.0f, acc[mt][nt][3])), ee2.y);
                    int r0 = mt * 2, r1 = mt * 2 + 1;
                    ins2(b0v[r0], b0i[r0], b1v[r0], b1i[r0], d0, code0);
                    ins2(b0v[r0], b0i[r0], b1v[r0], b1i[r0], d1, code0 + 1);
                    ins2(b0v[r1], b0i[r1], b1v[r1], b1i[r1], d2, code0);
                    ins2(b0v[r1], b0i[r1], b1v[r1], b1i[r1], d3, code0 + 1);
                    acc[mt][nt][0] = 0.f; acc[mt][nt][1] = 0.f;
                    acc[mt][nt][2] = 0.f; acc[mt][nt][3] = 0.f;
                }
            }
        }
    }

    __syncthreads();
#pragma unroll
    for (int i = 0; i < 4; i++) {
        float v0 = b0v[i], v1 = b1v[i]; int i0 = b0i[i], i1 = b1i[i];
#pragma unroll
        for (int o = 1; o <= 2; o <<= 1) {
            float ov0 = __shfl_xor_sync(0xffffffffu, v0, o);
            int   oi0 = __shfl_xor_sync(0xffffffffu, i0, o);
            float ov1 = __shfl_xor_sync(0xffffffffu, v1, o);
            int   oi1 = __shfl_xor_sync(0xffffffffu, i1, o);
            ins2(v0, i0, v1, i1, ov0, oi0);
            ins2(v0, i0, v1, i1, ov1, oi1);
        }
        if (tig == 0) {
            int row = mw + (i >> 1) * 16 + gq + (i & 1) * 8;
            int half = (w & 1) * 128;
            sB0v[half + row] = v0; sB0i[half + row] = i0;
            sB1v[half + row] = v1; sB1i[half + row] = i1;
        }
    }
    __syncthreads();
    if (tid < 128) {
        float v0 = sB0v[tid], v1 = sB1v[tid];
        int i0 = sB0i[tid], i1 = sB1i[tid];
        ins2(v0, i0, v1, i1, sB0v[128 + tid], sB0i[128 + tid]);
        ins2(v0, i0, v1, i1, sB1v[128 + tid], sB1i[128 + tid]);
        int n = cid * 128 + tid;
        g_idx[n] = i0;
        out[OFF_IDX + n] = (float)i0;
        if (__fadd_rn(v1, -v0) < EPS_GAP) {
            int pos = atomicAdd(&g_fixn, 1);
            if (pos < NPTS) {
                g_fixlist[pos] = n;
                int l = atomicAdd(&s_fcnt, 1);
                s_fN[l] = n; s_fP[l] = pos;
            }
        }
    }
    // ---- gather flagged z rows into compacted g_zfix (coalesced consumer reads) ----
    __syncthreads();
    int fc = s_fcnt;
    for (int e = 0; e < fc; e++) {
        int n2 = s_fN[e], pos2 = s_fP[e];
        int b2 = n2 >> 10, hw2 = n2 & 1023;
        g_zfix[(size_t)pos2 * DIM + tid] = z[((size_t)b2 * DIM + tid) * HW + hw2];
        if (tid == 0) g_zzfix[pos2] = g_zz[n2];
    }
}

// ---------------- rescue v7: exact fp32 scan, 4pts x 2codes, shuffle reduce ----------------
#define FROW 65
#define EROW 65
#define SMFX_E  (32 * FROW * 16)                    // 33280
#define SMFX_ZZ (SMFX_E + 64 * EROW * 16)           // 99840
#define SMEM_FIX (SMFX_ZZ + 128)                    // 99968
__global__ __launch_bounds__(256) void k_fix(const float* __restrict__ E) {
    extern __shared__ uint8_t sm[];
    float4* s_z4 = reinterpret_cast<float4*>(sm);              // [32][FROW]
    float4* s_e4 = reinterpret_cast<float4*>(sm + SMFX_E);     // [64][EROW]
    float*  s_zzl = reinterpret_cast<float*>(sm + SMFX_ZZ);

    const int tid = threadIdx.x;
    const int tx = tid & 31, ty = tid >> 5;
    int cnt = min(g_fixn, NPTS);
    int nwork = ((cnt + 31) >> 5) * 16;

    for (int wi = blockIdx.x; wi < nwork; wi += gridDim.x) {
        int g = wi >> 4, seg = wi & 15;
        int base = g * 32;
        int np = min(32, cnt - base);
        {
            const float4* zf4 = reinterpret_cast<const float4*>(g_zfix);
#pragma unroll
            for (int j = 0; j < 8; j++) {
                int idx = tid + j * 256;
                int row = idx >> 6, c4 = idx & 63;
                int rl = (row < np) ? row : 0;
                s_z4[row * FROW + c4] = zf4[(size_t)(base + rl) * 64 + c4];
            }
            if (tid < 32) {
                int rl = (tid < np) ? tid : 0;
                s_zzl[tid] = g_zzfix[base + rl];
            }
        }
        {
            int cbase = seg * 64;
            const float4* E4 = reinterpret_cast<const float4*>(E) + (size_t)cbase * 64;
#pragma unroll
            for (int j = 0; j < 16; j++) {
                int idx = tid + j * 256;
                int c = idx >> 6, k4 = idx & 63;
                s_e4[k4 * EROW + c] = E4[c * 64 + k4];
            }
        }
        __syncthreads();

        int cbase = seg * 64;
        float a[4][2];
#pragma unroll
        for (int p = 0; p < 4; p++) { a[p][0] = 0.f; a[p][1] = 0.f; }
#pragma unroll 8
        for (int k4 = 0; k4 < 64; k4++) {
            float4 e0 = s_e4[k4 * EROW + tx];
            float4 e1 = s_e4[k4 * EROW + tx + 32];
#pragma unroll
            for (int p = 0; p < 4; p++) {
                float4 zv = s_z4[(ty + 8 * p) * FROW + k4];
                a[p][0] = fmaf(zv.x, e0.x, a[p][0]); a[p][0] = fmaf(zv.y, e0.y, a[p][0]);
                a[p][0] = fmaf(zv.z, e0.z, a[p][0]); a[p][0] = fmaf(zv.w, e0.w, a[p][0]);
                a[p][1] = fmaf(zv.x, e1.x, a[p][1]); a[p][1] = fmaf(zv.y, e1.y, a[p][1]);
                a[p][1] = fmaf(zv.z, e1.z, a[p][1]); a[p][1] = fmaf(zv.w, e1.w, a[p][1]);
            }
        }
        int c0 = cbase + tx, c1 = cbase + tx + 32;
        float ee0 = g_ee[c0], ee1 = g_ee[c1];
#pragma unroll
        for (int p = 0; p < 4; p++) {
            float zzp = s_zzl[ty + 8 * p];
            float d0 = __fadd_rn(__fadd_rn(zzp, -__fmul_rn(2.0f, a[p][0])), ee0);
            float d1 = __fadd_rn(__fadd_rn(zzp, -__fmul_rn(2.0f, a[p][1])), ee1);
            float bv; int bi;
            if (d0 < d1 || (d0 == d1 && c0 < c1)) { bv = d0; bi = c0; }
            else { bv = d1; bi = c1; }
#pragma unroll
            for (int o = 16; o; o >>= 1) {
                float ov = __shfl_xor_sync(0xffffffffu, bv, o);
                int oi = __shfl_xor_sync(0xffffffffu, bi, o);
                upd1(bv, bi, ov, oi);
            }
            if (tx == 0) {
                int row = ty + 8 * p;
                if (row < np) {
                    int n = g_fixlist[base + row];
                    unsigned long long key =
                        ((unsigned long long)__float_as_uint(bv) << 32) | (unsigned int)bi;
                    atomicMin(&g_best[n], key);
                }
            }
        }
        __syncthreads();
    }
}

// ---------------- fused epilogue (+ rescued-index finalize): z_q, loss, counts, es ----------------
__global__ __launch_bounds__(256)
void k_epi(const float* __restrict__ z, const float* __restrict__ E,
           float* __restrict__ out) {
    __shared__ float tile[64 * 129];
    __shared__ float lred[8];
    __shared__ int s_code[128];
    const int tid = threadIdx.x;
    const int n0 = blockIdx.x * 128;
    const int b = n0 >> 10, hw0 = n0 & 1023;
    const float* zb = z + (size_t)b * DIM * HW + hw0;
    float* ob = out + OFF_ZQ + (size_t)b * DIM * HW + hw0;
    const int w = tid >> 5, lane = tid & 31;
    float lacc = 0.f;

    if (tid < 128) {
        int n = n0 + tid;
        unsigned long long bst = g_best[n];
        int code = (bst != 0xFFFFFFFFFFFFFFFFull)
                       ? (int)(unsigned int)(bst & 0xFFFFFFFFull)
                       : g_idx[n];
        s_code[tid] = code;
        out[OFF_IDX + n] = (float)code;
    }

    for (int c = 0; c < 4; c++) {
#pragma unroll
        for (int r = 0; r < 32; r++) {
            int idx = tid + r * 256;
            int dd = idx >> 7, pt = idx & 127;
            tile[dd * 129 + pt] = zb[(size_t)(c * 64 + dd) * HW + pt];
        }
        __syncthreads();
        for (int q = 0; q < 16; q++) {
            int pt = w * 16 + q;
            int code = s_code[pt];
            int d = c * 64 + lane * 2;
            float2 ev = *reinterpret_cast<const float2*>(&E[(size_t)code * DIM + d]);
            float z0 = tile[(lane * 2) * 129 + pt];
            float z1 = tile[(lane * 2 + 1) * 129 + pt];
            float d0 = __fadd_rn(z0, -ev.x);
            float d1 = __fadd_rn(z1, -ev.y);
            lacc = fmaf(d0, d0, lacc);
            lacc = fmaf(d1, d1, lacc);
            float o0 = __fadd_rn(z0, __fadd_rn(ev.x, -z0));
            float o1 = __fadd_rn(z1, __fadd_rn(ev.y, -z1));
            tile[(lane * 2) * 129 + pt] = o0;
            tile[(lane * 2 + 1) * 129 + pt] = o1;
            atomicAdd(reinterpret_cast<float2*>(&g_es[(size_t)code * DIM + d]),
                      make_float2(z0, z1));
        }
        __syncthreads();
#pragma unroll
        for (int r = 0; r < 32; r++) {
            int idx = tid + r * 256;
            int dd = idx >> 7, pt = idx & 127;
            ob[(size_t)(c * 64 + dd) * HW + pt] = tile[dd * 129 + pt];
        }
        __syncthreads();
    }
    if (tid < 128) atomicAdd(&g_counts[s_code[tid]], 1.0f);
#pragma unroll
    for (int o = 16; o; o >>= 1) lacc += __shfl_xor_sync(0xffffffffu, lacc, o);
    if (!lane) lred[w] = lacc;
    __syncthreads();
    if (tid == 0) {
        float s = 0.f;
#pragma unroll
        for (int i = 0; i < 8; i++) s += lred[i];
        atomicAdd(&g_loss, s);
    }
}

// ---------------- new_cs + n + loss scalar ----------------
__global__ void k4a(const float* __restrict__ ema_cs, float* __restrict__ out) {
    __shared__ float red[32];
    int k = threadIdx.x;
    float ncs = __fadd_rn(__fmul_rn(0.99f, ema_cs[k]), __fmul_rn(0.01f, g_counts[k]));
    g_newcs[k] = ncs;
    out[OFF_CS + k] = ncs;
    float s = ncs;
#pragma unroll
    for (int o = 16; o; o >>= 1) s += __shfl_xor_sync(0xffffffffu, s, o);
    if ((k & 31) == 0) red[k >> 5] = s;
    __syncthreads();
    if (k < 32) {
        float v = red[k];
#pragma unroll
        for (int o = 16; o; o >>= 1) v += __shfl_xor_sync(0xffffffffu, v, o);
        if (!k) {
            g_nsum = v;
            out[OFF_LOSS] = g_loss * (1.0f / 8388608.0f);
        }
    }
}

// ---------------- new_es + new_embedding ----------------
__global__ void k4b(const float* __restrict__ ema_es, float* __restrict__ out) {
    int k = blockIdx.x, d = threadIdx.x;
    size_t i = (size_t)k * DIM + d;
    float es = __fadd_rn(__fmul_rn(0.99f, ema_es[i]), __fmul_rn(0.01f, g_es[i]));
    out[OFF_ES + i] = es;
    float n = g_nsum;
    float cs = __fmul_rn(__fdiv_rn(__fadd_rn(g_newcs[k], 1e-5f),
                                   __fadd_rn(n, 0.01024f)), n);
    out[OFF_EMB + i] = __fdiv_rn(es, cs);
}

extern "C" void kernel_launch(void* const* d_in, const int* in_sizes, int n_in,
                              void* d_out, int out_size) {
    const float* z      = (const float*)d_in[0];
    const float* E      = (const float*)d_in[1];
    const float* ema_cs = (const float*)d_in[2];
    const float* ema_es = (const float*)d_in[3];
    float* out = (float*)d_out;

    cudaFuncSetAttribute(k_gemm, cudaFuncAttributeMaxDynamicSharedMemorySize, SMEM_GEMM);
    cudaFuncSetAttribute(k_fix, cudaFuncAttributeMaxDynamicSharedMemorySize, SMEM_FIX);

    k_prep<<<PREP_BLOCKS, 256>>>(E, z);          // 1: all prep
    k_gemm<<<256, 256, SMEM_GEMM>>>(z, out);     // 2: gemm + top2 + z gather
    k_fix<<<296, 256, SMEM_FIX>>>(E);            // 3: rescue
    k_epi<<<NPTS / 128, 256>>>(z, E, out);       // 4  <- ncu captures this
    k4a<<<1, 1024>>>(ema_cs, out);               // 5
    k4b<<<KCODES, DIM>>>(ema_es, out);           // 6
}